// round 9
// baseline (speedup 1.0000x reference)
#include <cuda_runtime.h>
#include <cuda_bf16.h>
#include <mma.h>
#include <math.h>
#include <stdint.h>

using namespace nvcuda;

#define B_ 8
#define T_ 128
#define S_ 256
#define H_ 512

// fp32 scratch
__device__ float g_qs[B_ * T_ * H_];                 // 2 MB
__device__ float g_hs[B_ * S_ * H_];                 // 4 MB
__device__ float g_ppq[2][B_ * T_ * H_];             // 4 MB  qs split-K partials
__device__ float g_pph[2][B_ * S_ * H_];             // 8 MB  hs split-K partials
__device__ float g_po[4][B_ * T_ * H_];              // 8 MB  out split-K partials
// bf16 hi/lo pre-split operands
__device__ __nv_bfloat16 g_qhi[B_ * T_ * H_],  g_qlo[B_ * T_ * H_];
__device__ __nv_bfloat16 g_ehi[B_ * S_ * H_],  g_elo[B_ * S_ * H_];
__device__ __nv_bfloat16 g_wshi[H_ * H_],      g_wslo[H_ * H_];
__device__ __nv_bfloat16 g_whhi[H_ * H_],      g_whlo[H_ * H_];
__device__ __nv_bfloat16 g_wohi[H_ * 2 * H_],  g_wolo[H_ * 2 * H_];
__device__ __nv_bfloat16 g_chi[B_ * T_ * H_],  g_clo[B_ * T_ * H_];

// ---------------------------------------------------------------------------
__device__ __forceinline__ void bsplit(float x, __nv_bfloat16& hi, __nv_bfloat16& lo) {
    hi = __float2bfloat16(x);
    lo = __float2bfloat16(x - __bfloat162float(hi));
}
__device__ __forceinline__ uint32_t smem_u32(const void* p) {
    uint32_t a;
    asm("{ .reg .u64 t; cvta.to.shared.u64 t, %1; cvt.u32.u64 %0, t; }"
        : "=r"(a) : "l"(p));
    return a;
}
__device__ __forceinline__ void cpa16(uint32_t d, const void* s) {
    asm volatile("cp.async.cg.shared.global [%0], [%1], 16;" :: "r"(d), "l"(s));
}
#define CP_COMMIT() asm volatile("cp.async.commit_group;" ::: "memory")
#define CP_WAIT1()  asm volatile("cp.async.wait_group 1;" ::: "memory")
#define CP_WAIT0()  asm volatile("cp.async.wait_group 0;" ::: "memory")

// ---------------------------------------------------------------------------
// convert: split inputs + weights into bf16 hi/lo (one float4 per thread)
// ---------------------------------------------------------------------------
__global__ void __launch_bounds__(256) convert_kernel(
    const float* __restrict__ query, const float* __restrict__ enc,
    const float* __restrict__ W_s, const float* __restrict__ W_h,
    const float* __restrict__ W_out)
{
    const int i4 = blockIdx.x * 256 + threadIdx.x;
    const float* src;
    __nv_bfloat16 *dhi, *dlo;
    int off;
    if (i4 < 131072)      { src = query; dhi = g_qhi;  dlo = g_qlo;  off = i4; }
    else if (i4 < 393216) { src = enc;   dhi = g_ehi;  dlo = g_elo;  off = i4 - 131072; }
    else if (i4 < 458752) { src = W_s;   dhi = g_wshi; dlo = g_wslo; off = i4 - 393216; }
    else if (i4 < 524288) { src = W_h;   dhi = g_whhi; dlo = g_whlo; off = i4 - 458752; }
    else                  { src = W_out; dhi = g_wohi; dlo = g_wolo; off = i4 - 524288; }

    const float4 v = reinterpret_cast<const float4*>(src)[off];
    union { __nv_bfloat16 h[4]; uint2 u; } ph, pl;
    bsplit(v.x, ph.h[0], pl.h[0]); bsplit(v.y, ph.h[1], pl.h[1]);
    bsplit(v.z, ph.h[2], pl.h[2]); bsplit(v.w, ph.h[3], pl.h[3]);
    reinterpret_cast<uint2*>(dhi)[off] = ph.u;
    reinterpret_cast<uint2*>(dlo)[off] = pl.u;
}

// ---------------------------------------------------------------------------
// Split-K wmma GEMM (bf16 3-term compensation), fp32 partial output.
// Tile 64x64, 256 threads, 8 warps (warp tile 16x32), K-chunk 32, 2-stage.
// ---------------------------------------------------------------------------
#define PITCH 40
#define TILE_B (64 * PITCH * 2)          // 5120 B
#define AHI_O 0
#define ALO_O (TILE_B)
#define BHI_O (2 * TILE_B)
#define BLO_O (3 * TILE_B)
#define BUF_B (4 * TILE_B)               // 20480 B per stage
#define SMEM_BYTES (2 * BUF_B)           // 40960 B

__device__ __forceinline__ void issue_chunk(
    uint32_t sb,
    const __nv_bfloat16* __restrict__ Ahi, const __nv_bfloat16* __restrict__ Alo,
    const __nv_bfloat16* __restrict__ Bhi, const __nv_bfloat16* __restrict__ Blo,
    int ldb, int m0, int n0, int aoff, int boff, int tid)
{
    const int row = tid >> 2, seg = tid & 3;       // 64 rows x 4 x 16B
    const uint32_t soff = (uint32_t)(row * (PITCH * 2) + seg * 16);
    const size_t ao = (size_t)(m0 + row) * H_ + aoff + seg * 8;
    const size_t bo = (size_t)(n0 + row) * ldb + boff + seg * 8;
    cpa16(sb + AHI_O + soff, Ahi + ao);
    cpa16(sb + ALO_O + soff, Alo + ao);
    cpa16(sb + BHI_O + soff, Bhi + bo);
    cpa16(sb + BLO_O + soff, Blo + bo);
}

__device__ __forceinline__ void gemm_sk(
    char* smem,
    const __nv_bfloat16* __restrict__ Ahi, const __nv_bfloat16* __restrict__ Alo,
    const __nv_bfloat16* __restrict__ Bhi, const __nv_bfloat16* __restrict__ Blo,
    int ldb, float* __restrict__ Cpart,
    int m0, int n0, int akbeg, int bkbeg, int nchunks)
{
    const int tid  = threadIdx.x;
    const int wid  = tid >> 5;
    const int m0w  = (wid >> 1) * 16;    // 4 m-warps x 16 rows
    const int n0w  = (wid & 1) * 32;     // 2 n-warps x 32 cols
    const uint32_t sb = smem_u32(smem);

    wmma::fragment<wmma::accumulator, 16, 16, 16, float> acc[2];
    wmma::fill_fragment(acc[0], 0.0f);
    wmma::fill_fragment(acc[1], 0.0f);

    issue_chunk(sb, Ahi, Alo, Bhi, Blo, ldb, m0, n0, akbeg, bkbeg, tid);
    CP_COMMIT();

    #pragma unroll 1
    for (int it = 0; it < nchunks; ++it) {
        if (it + 1 < nchunks) {
            issue_chunk(sb + ((it + 1) & 1) * BUF_B, Ahi, Alo, Bhi, Blo,
                        ldb, m0, n0, akbeg + (it + 1) * 32, bkbeg + (it + 1) * 32, tid);
            CP_COMMIT();
            CP_WAIT1();
        } else {
            CP_WAIT0();
        }
        __syncthreads();

        const char* buf = smem + (it & 1) * BUF_B;
        const __nv_bfloat16* sAhi = reinterpret_cast<const __nv_bfloat16*>(buf + AHI_O);
        const __nv_bfloat16* sAlo = reinterpret_cast<const __nv_bfloat16*>(buf + ALO_O);
        const __nv_bfloat16* sBhi = reinterpret_cast<const __nv_bfloat16*>(buf + BHI_O);
        const __nv_bfloat16* sBlo = reinterpret_cast<const __nv_bfloat16*>(buf + BLO_O);

        #pragma unroll
        for (int kf = 0; kf < 2; kf++) {
            const int ko = kf * 16;
            wmma::fragment<wmma::matrix_a, 16, 16, 16, __nv_bfloat16, wmma::row_major> ahi, alo;
            wmma::fragment<wmma::matrix_b, 16, 16, 16, __nv_bfloat16, wmma::col_major> bhi[2], blo[2];
            wmma::load_matrix_sync(ahi, &sAhi[m0w * PITCH + ko], PITCH);
            wmma::load_matrix_sync(alo, &sAlo[m0w * PITCH + ko], PITCH);
            #pragma unroll
            for (int ni = 0; ni < 2; ni++) {
                wmma::load_matrix_sync(bhi[ni], &sBhi[(n0w + 16 * ni) * PITCH + ko], PITCH);
                wmma::load_matrix_sync(blo[ni], &sBlo[(n0w + 16 * ni) * PITCH + ko], PITCH);
            }
            #pragma unroll
            for (int ni = 0; ni < 2; ni++) {
                wmma::mma_sync(acc[ni], ahi, bhi[ni], acc[ni]);
                wmma::mma_sync(acc[ni], ahi, blo[ni], acc[ni]);
                wmma::mma_sync(acc[ni], alo, bhi[ni], acc[ni]);
            }
        }
        __syncthreads();
    }

    #pragma unroll
    for (int ni = 0; ni < 2; ni++)
        wmma::store_matrix_sync(
            &Cpart[(size_t)(m0 + m0w) * H_ + n0 + n0w + 16 * ni],
            acc[ni], H_, wmma::mem_row_major);
}

// proj: grid (8, 48, 2). y<16 -> qs partial; else hs partial. kz splits K=512 in 2.
__global__ void __launch_bounds__(256) proj_wmma()
{
    __shared__ __align__(16) char smem[SMEM_BYTES];
    const int n0 = blockIdx.x * 64;
    const int my = blockIdx.y;
    const int kz = blockIdx.z;
    const int kb = kz * 256;
    if (my < 16)
        gemm_sk(smem, g_qhi, g_qlo, g_wshi, g_wslo, H_,
                g_ppq[kz], my * 64, n0, kb, kb, 8);
    else
        gemm_sk(smem, g_ehi, g_elo, g_whhi, g_whlo, H_,
                g_pph[kz], (my - 16) * 64, n0, kb, kb, 8);
}

// preduce: qs = ppq0+ppq1; hs = pph0+pph1  (393216 float4s -> 1536 blocks)
__global__ void __launch_bounds__(256) preduce_kernel()
{
    const int i4 = blockIdx.x * 256 + threadIdx.x;
    if (i4 < 131072) {
        const float4 a = reinterpret_cast<const float4*>(g_ppq[0])[i4];
        const float4 b = reinterpret_cast<const float4*>(g_ppq[1])[i4];
        reinterpret_cast<float4*>(g_qs)[i4] =
            make_float4(a.x + b.x, a.y + b.y, a.z + b.z, a.w + b.w);
    } else {
        const int j = i4 - 131072;
        const float4 a = reinterpret_cast<const float4*>(g_pph[0])[j];
        const float4 b = reinterpret_cast<const float4*>(g_pph[1])[j];
        reinterpret_cast<float4*>(g_hs)[j] =
            make_float4(a.x + b.x, a.y + b.y, a.z + b.z, a.w + b.w);
    }
}

// out: grid (8, 16, 4). kz<2 reads ctx, kz>=2 reads query (concat-aligned split-K).
__global__ void __launch_bounds__(256) out_wmma()
{
    __shared__ __align__(16) char smem[SMEM_BYTES];
    const int kz = blockIdx.z;
    const __nv_bfloat16* Ahi = (kz < 2) ? g_chi : g_qhi;
    const __nv_bfloat16* Alo = (kz < 2) ? g_clo : g_qlo;
    gemm_sk(smem, Ahi, Alo, g_wohi, g_wolo, 2 * H_,
            g_po[kz], blockIdx.y * 64, blockIdx.x * 64,
            (kz & 1) * 256, kz * 256, 8);
}

// oreduce: out = tanh(p0+p1+p2+p3 + bias)  (131072 float4s -> 512 blocks)
__global__ void __launch_bounds__(256) oreduce_kernel(
    const float* __restrict__ bias, float* __restrict__ out)
{
    const int i4 = blockIdx.x * 256 + threadIdx.x;
    const float4 p0 = reinterpret_cast<const float4*>(g_po[0])[i4];
    const float4 p1 = reinterpret_cast<const float4*>(g_po[1])[i4];
    const float4 p2 = reinterpret_cast<const float4*>(g_po[2])[i4];
    const float4 p3 = reinterpret_cast<const float4*>(g_po[3])[i4];
    const float4 bb = *reinterpret_cast<const float4*>(&bias[(i4 & 127) * 4]);
    float4 o;
    o.x = tanhf(p0.x + p1.x + p2.x + p3.x + bb.x);
    o.y = tanhf(p0.y + p1.y + p2.y + p3.y + bb.y);
    o.z = tanhf(p0.z + p1.z + p2.z + p3.z + bb.z);
    o.w = tanhf(p0.w + p1.w + p2.w + p3.w + bb.w);
    reinterpret_cast<float4*>(out)[i4] = o;
}

// ---------------------------------------------------------------------------
// Fused attention, TT=8, length-aware, double-buffered pass1 with SC=8
// (2x16KB buffers, one sync per chunk), dual accumulators.
// smem: 32KB + 8KB + 32B = 41KB < 48KB static limit.
// ---------------------------------------------------------------------------
#define TT 8
#define SC 8

__global__ void __launch_bounds__(256) attn_kernel(
    const float* __restrict__ enc, const float* __restrict__ v,
    const int* __restrict__ lens)
{
    __shared__ float sh_hs[2][SC * H_];       // 32 KB double buffer
    __shared__ float sh_sc[TT][S_];           // 8 KB
    __shared__ float sh_rsum[TT];

    const int b    = blockIdx.y;
    const int t0   = blockIdx.x * TT;
    const int tid  = threadIdx.x;
    const int lane = tid & 31;
    const int wid  = tid >> 5;                // one warp per t row

    const int len = lens[b];
    const int nch = (len + SC - 1) / SC;      // 16..32 chunks

    float qreg[16], vreg[16];
    {
        const float* qrow = g_qs + (size_t)(b * T_ + t0 + wid) * H_;
        #pragma unroll
        for (int j = 0; j < 16; j++) {
            qreg[j] = qrow[lane + 32 * j];
            vreg[j] = v[lane + 32 * j];
        }
    }

    const float* hsb  = g_hs + (size_t)b * S_ * H_;
    const float* encb = enc  + (size_t)b * S_ * H_;

    // ---- Pass 1: double-buffered (SC=8: 4 float4/thread), one sync/chunk ----
    float4 r[4];
    #pragma unroll
    for (int q = 0; q < 4; q++)
        r[q] = *reinterpret_cast<const float4*>(&hsb[(q * 256 + tid) * 4]);
    #pragma unroll
    for (int q = 0; q < 4; q++)
        *reinterpret_cast<float4*>(&sh_hs[0][(q * 256 + tid) * 4]) = r[q];

    #pragma unroll 1
    for (int it = 0; it < nch; ++it) {
        if (it + 1 < nch) {
            const float* nxt = &hsb[(size_t)(it + 1) * SC * H_];
            #pragma unroll
            for (int q = 0; q < 4; q++)
                r[q] = *reinterpret_cast<const float4*>(&nxt[(q * 256 + tid) * 4]);
        }
        __syncthreads();   // buf[it&1] ready; all warps done with buf[(it+1)&1]

        const float* base = sh_hs[it & 1];
        const int s0 = it * SC;
        #pragma unroll
        for (int i = 0; i < SC; i++) {
            const float* hrow = &base[i * H_];
            float a0 = 0.f, a1 = 0.f;
            #pragma unroll
            for (int j = 0; j < 16; j += 2) {
                const float x0 = qreg[j] + hrow[lane + 32 * j];
                const float x1 = qreg[j + 1] + hrow[lane + 32 * (j + 1)];
                float t0f, t1f;
                asm("tanh.approx.f32 %0, %1;" : "=f"(t0f) : "f"(x0));
                asm("tanh.approx.f32 %0, %1;" : "=f"(t1f) : "f"(x1));
                a0 = fmaf(t0f, vreg[j], a0);
                a1 = fmaf(t1f, vreg[j + 1], a1);
            }
            float acc = a0 + a1;
            acc += __shfl_xor_sync(0xffffffffu, acc, 16);
            acc += __shfl_xor_sync(0xffffffffu, acc, 8);
            acc += __shfl_xor_sync(0xffffffffu, acc, 4);
            acc += __shfl_xor_sync(0xffffffffu, acc, 2);
            acc += __shfl_xor_sync(0xffffffffu, acc, 1);
            if (lane == 0) sh_sc[wid][s0 + i] = acc;
        }

        if (it + 1 < nch) {
            float* dst = sh_hs[(it + 1) & 1];
            #pragma unroll
            for (int q = 0; q < 4; q++)
                *reinterpret_cast<float4*>(&dst[(q * 256 + tid) * 4]) = r[q];
        }
    }
    __syncthreads();

    // ---- Softmax (warp per t row) ----
    {
        const int t = wid;
        float vals[S_ / 32];
        float m = -1e30f;
        #pragma unroll
        for (int i = 0; i < S_ / 32; i++) {
            const int s = lane + 32 * i;
            const float sc = (s < len) ? sh_sc[t][s] : -1e30f;
            vals[i] = sc;
            m = fmaxf(m, sc);
        }
        #pragma unroll
        for (int o = 16; o; o >>= 1) m = fmaxf(m, __shfl_xor_sync(0xffffffffu, m, o));
        float sum = 0.f;
        #pragma unroll
        for (int i = 0; i < S_ / 32; i++) {
            const int s = lane + 32 * i;
            const float e = (s < len) ? __expf(vals[i] - m) : 0.f;
            sh_sc[t][s] = e;
            sum += e;
        }
        #pragma unroll
        for (int o = 16; o; o >>= 1) sum += __shfl_xor_sync(0xffffffffu, sum, o);
        if (lane == 0) sh_rsum[t] = 1.0f / sum;
    }
    __syncthreads();

    // ---- Pass 2: context over s in [0,len), split evenly across halves ----
    const int g  = tid >> 7;
    const int c4 = tid & 127;
    const int half = len >> 1;
    const int sbeg = g ? half : 0;
    const int send = g ? len : half;

    float4 acc4[TT];
    #pragma unroll
    for (int t = 0; t < TT; t++) acc4[t] = make_float4(0.f, 0.f, 0.f, 0.f);

    #pragma unroll 4
    for (int s = sbeg; s < send; s++) {
        const float4 e4 = *reinterpret_cast<const float4*>(&encb[(size_t)s * H_ + c4 * 4]);
        #pragma unroll
        for (int t = 0; t < TT; t++) {
            const float w = sh_sc[t][s];
            acc4[t].x = fmaf(w, e4.x, acc4[t].x);
            acc4[t].y = fmaf(w, e4.y, acc4[t].y);
            acc4[t].z = fmaf(w, e4.z, acc4[t].z);
            acc4[t].w = fmaf(w, e4.w, acc4[t].w);
        }
    }

    if (g == 0) {
        #pragma unroll
        for (int t = 0; t < TT; t++)
            *reinterpret_cast<float4*>(&sh_hs[0][(t * 128 + c4) * 4]) = acc4[t];
    }
    __syncthreads();
    if (g == 1) {
        #pragma unroll
        for (int t = 0; t < TT; t++) {
            float4 o = *reinterpret_cast<const float4*>(&sh_hs[0][(t * 128 + c4) * 4]);
            const float rs = sh_rsum[t];
            o.x = (o.x + acc4[t].x) * rs;
            o.y = (o.y + acc4[t].y) * rs;
            o.z = (o.z + acc4[t].z) * rs;
            o.w = (o.w + acc4[t].w) * rs;
            union { __nv_bfloat16 h[4]; uint2 u; } ph, pl;
            bsplit(o.x, ph.h[0], pl.h[0]); bsplit(o.y, ph.h[1], pl.h[1]);
            bsplit(o.z, ph.h[2], pl.h[2]); bsplit(o.w, ph.h[3], pl.h[3]);
            const size_t off = (size_t)(b * T_ + t0 + t) * H_ + c4 * 4;
            *reinterpret_cast<uint2*>(&g_chi[off]) = ph.u;
            *reinterpret_cast<uint2*>(&g_clo[off]) = pl.u;
        }
    }
}

// ---------------------------------------------------------------------------
extern "C" void kernel_launch(void* const* d_in, const int* in_sizes, int n_in,
                              void* d_out, int out_size)
{
    const float* query = (const float*)d_in[0];
    const float* enc   = (const float*)d_in[1];
    const int*   lens  = (const int*)d_in[2];
    const float* W_s   = (const float*)d_in[3];
    const float* W_h   = (const float*)d_in[4];
    const float* v     = (const float*)d_in[5];
    const float* W_out = (const float*)d_in[6];
    const float* b_out = (const float*)d_in[7];
    float* out = (float*)d_out;

    convert_kernel<<<2560, 256>>>(query, enc, W_s, W_h, W_out);
    proj_wmma<<<dim3(8, 48, 2), 256>>>();
    preduce_kernel<<<1536, 256>>>();
    attn_kernel<<<dim3(T_ / TT, B_), 256>>>(enc, v, lens);
    out_wmma<<<dim3(8, 16, 4), 256>>>();
    oreduce_kernel<<<512, 256>>>(b_out, out);
}

// round 10
// speedup vs baseline: 1.2439x; 1.2439x over previous
#include <cuda_runtime.h>
#include <cuda_bf16.h>
#include <mma.h>
#include <math.h>
#include <stdint.h>

using namespace nvcuda;

#define B_ 8
#define T_ 128
#define S_ 256
#define H_ 512

// fp32 scratch
__device__ float g_qs[B_ * T_ * H_];                 // 2 MB
__device__ float g_hs[B_ * S_ * H_];                 // 4 MB
__device__ float g_ppq[2][B_ * T_ * H_];             // 4 MB  qs split-K partials
__device__ float g_pph[2][B_ * S_ * H_];             // 8 MB  hs split-K partials
__device__ float g_po[4][B_ * T_ * H_];              // 8 MB  out split-K partials
// bf16 hi/lo pre-split operands
__device__ __nv_bfloat16 g_qhi[B_ * T_ * H_],  g_qlo[B_ * T_ * H_];
__device__ __nv_bfloat16 g_ehi[B_ * S_ * H_],  g_elo[B_ * S_ * H_];
__device__ __nv_bfloat16 g_wshi[H_ * H_],      g_wslo[H_ * H_];
__device__ __nv_bfloat16 g_whhi[H_ * H_],      g_whlo[H_ * H_];
__device__ __nv_bfloat16 g_wohi[H_ * 2 * H_],  g_wolo[H_ * 2 * H_];
__device__ __nv_bfloat16 g_chi[B_ * T_ * H_],  g_clo[B_ * T_ * H_];

// ---------------------------------------------------------------------------
__device__ __forceinline__ void bsplit(float x, __nv_bfloat16& hi, __nv_bfloat16& lo) {
    hi = __float2bfloat16(x);
    lo = __float2bfloat16(x - __bfloat162float(hi));
}
__device__ __forceinline__ uint32_t smem_u32(const void* p) {
    uint32_t a;
    asm("{ .reg .u64 t; cvta.to.shared.u64 t, %1; cvt.u32.u64 %0, t; }"
        : "=r"(a) : "l"(p));
    return a;
}
__device__ __forceinline__ void cpa16(uint32_t d, const void* s) {
    asm volatile("cp.async.cg.shared.global [%0], [%1], 16;" :: "r"(d), "l"(s));
}
#define CP_COMMIT() asm volatile("cp.async.commit_group;" ::: "memory")
#define CP_WAIT1()  asm volatile("cp.async.wait_group 1;" ::: "memory")
#define CP_WAIT0()  asm volatile("cp.async.wait_group 0;" ::: "memory")

// ---------------------------------------------------------------------------
// convert: split inputs + weights into bf16 hi/lo (one float4 per thread)
// ---------------------------------------------------------------------------
__global__ void __launch_bounds__(256) convert_kernel(
    const float* __restrict__ query, const float* __restrict__ enc,
    const float* __restrict__ W_s, const float* __restrict__ W_h,
    const float* __restrict__ W_out)
{
    const int i4 = blockIdx.x * 256 + threadIdx.x;
    const float* src;
    __nv_bfloat16 *dhi, *dlo;
    int off;
    if (i4 < 131072)      { src = query; dhi = g_qhi;  dlo = g_qlo;  off = i4; }
    else if (i4 < 393216) { src = enc;   dhi = g_ehi;  dlo = g_elo;  off = i4 - 131072; }
    else if (i4 < 458752) { src = W_s;   dhi = g_wshi; dlo = g_wslo; off = i4 - 393216; }
    else if (i4 < 524288) { src = W_h;   dhi = g_whhi; dlo = g_whlo; off = i4 - 458752; }
    else                  { src = W_out; dhi = g_wohi; dlo = g_wolo; off = i4 - 524288; }

    const float4 v = reinterpret_cast<const float4*>(src)[off];
    union { __nv_bfloat16 h[4]; uint2 u; } ph, pl;
    bsplit(v.x, ph.h[0], pl.h[0]); bsplit(v.y, ph.h[1], pl.h[1]);
    bsplit(v.z, ph.h[2], pl.h[2]); bsplit(v.w, ph.h[3], pl.h[3]);
    reinterpret_cast<uint2*>(dhi)[off] = ph.u;
    reinterpret_cast<uint2*>(dlo)[off] = pl.u;
}

// ---------------------------------------------------------------------------
// Split-K wmma GEMM (bf16 3-term compensation), fp32 partial output.
// Tile 64x64, 256 threads, 8 warps (warp tile 16x32), K-chunk 32, 2-stage.
// ---------------------------------------------------------------------------
#define PITCH 40
#define TILE_B (64 * PITCH * 2)          // 5120 B
#define AHI_O 0
#define ALO_O (TILE_B)
#define BHI_O (2 * TILE_B)
#define BLO_O (3 * TILE_B)
#define BUF_B (4 * TILE_B)               // 20480 B per stage
#define SMEM_BYTES (2 * BUF_B)           // 40960 B

__device__ __forceinline__ void issue_chunk(
    uint32_t sb,
    const __nv_bfloat16* __restrict__ Ahi, const __nv_bfloat16* __restrict__ Alo,
    const __nv_bfloat16* __restrict__ Bhi, const __nv_bfloat16* __restrict__ Blo,
    int ldb, int m0, int n0, int aoff, int boff, int tid)
{
    const int row = tid >> 2, seg = tid & 3;       // 64 rows x 4 x 16B
    const uint32_t soff = (uint32_t)(row * (PITCH * 2) + seg * 16);
    const size_t ao = (size_t)(m0 + row) * H_ + aoff + seg * 8;
    const size_t bo = (size_t)(n0 + row) * ldb + boff + seg * 8;
    cpa16(sb + AHI_O + soff, Ahi + ao);
    cpa16(sb + ALO_O + soff, Alo + ao);
    cpa16(sb + BHI_O + soff, Bhi + bo);
    cpa16(sb + BLO_O + soff, Blo + bo);
}

__device__ __forceinline__ void gemm_sk(
    char* smem,
    const __nv_bfloat16* __restrict__ Ahi, const __nv_bfloat16* __restrict__ Alo,
    const __nv_bfloat16* __restrict__ Bhi, const __nv_bfloat16* __restrict__ Blo,
    int ldb, float* __restrict__ Cpart,
    int m0, int n0, int akbeg, int bkbeg, int nchunks)
{
    const int tid  = threadIdx.x;
    const int wid  = tid >> 5;
    const int m0w  = (wid >> 1) * 16;    // 4 m-warps x 16 rows
    const int n0w  = (wid & 1) * 32;     // 2 n-warps x 32 cols
    const uint32_t sb = smem_u32(smem);

    wmma::fragment<wmma::accumulator, 16, 16, 16, float> acc[2];
    wmma::fill_fragment(acc[0], 0.0f);
    wmma::fill_fragment(acc[1], 0.0f);

    issue_chunk(sb, Ahi, Alo, Bhi, Blo, ldb, m0, n0, akbeg, bkbeg, tid);
    CP_COMMIT();

    #pragma unroll 1
    for (int it = 0; it < nchunks; ++it) {
        if (it + 1 < nchunks) {
            issue_chunk(sb + ((it + 1) & 1) * BUF_B, Ahi, Alo, Bhi, Blo,
                        ldb, m0, n0, akbeg + (it + 1) * 32, bkbeg + (it + 1) * 32, tid);
            CP_COMMIT();
            CP_WAIT1();
        } else {
            CP_WAIT0();
        }
        __syncthreads();

        const char* buf = smem + (it & 1) * BUF_B;
        const __nv_bfloat16* sAhi = reinterpret_cast<const __nv_bfloat16*>(buf + AHI_O);
        const __nv_bfloat16* sAlo = reinterpret_cast<const __nv_bfloat16*>(buf + ALO_O);
        const __nv_bfloat16* sBhi = reinterpret_cast<const __nv_bfloat16*>(buf + BHI_O);
        const __nv_bfloat16* sBlo = reinterpret_cast<const __nv_bfloat16*>(buf + BLO_O);

        #pragma unroll
        for (int kf = 0; kf < 2; kf++) {
            const int ko = kf * 16;
            wmma::fragment<wmma::matrix_a, 16, 16, 16, __nv_bfloat16, wmma::row_major> ahi, alo;
            wmma::fragment<wmma::matrix_b, 16, 16, 16, __nv_bfloat16, wmma::col_major> bhi[2], blo[2];
            wmma::load_matrix_sync(ahi, &sAhi[m0w * PITCH + ko], PITCH);
            wmma::load_matrix_sync(alo, &sAlo[m0w * PITCH + ko], PITCH);
            #pragma unroll
            for (int ni = 0; ni < 2; ni++) {
                wmma::load_matrix_sync(bhi[ni], &sBhi[(n0w + 16 * ni) * PITCH + ko], PITCH);
                wmma::load_matrix_sync(blo[ni], &sBlo[(n0w + 16 * ni) * PITCH + ko], PITCH);
            }
            #pragma unroll
            for (int ni = 0; ni < 2; ni++) {
                wmma::mma_sync(acc[ni], ahi, bhi[ni], acc[ni]);
                wmma::mma_sync(acc[ni], ahi, blo[ni], acc[ni]);
                wmma::mma_sync(acc[ni], alo, bhi[ni], acc[ni]);
            }
        }
        __syncthreads();
    }

    #pragma unroll
    for (int ni = 0; ni < 2; ni++)
        wmma::store_matrix_sync(
            &Cpart[(size_t)(m0 + m0w) * H_ + n0 + n0w + 16 * ni],
            acc[ni], H_, wmma::mem_row_major);
}

// proj: grid (8, 48, 2). y<16 -> qs partial; else hs partial. kz splits K=512 in 2.
__global__ void __launch_bounds__(256) proj_wmma()
{
    __shared__ __align__(16) char smem[SMEM_BYTES];
    const int n0 = blockIdx.x * 64;
    const int my = blockIdx.y;
    const int kz = blockIdx.z;
    const int kb = kz * 256;
    if (my < 16)
        gemm_sk(smem, g_qhi, g_qlo, g_wshi, g_wslo, H_,
                g_ppq[kz], my * 64, n0, kb, kb, 8);
    else
        gemm_sk(smem, g_ehi, g_elo, g_whhi, g_whlo, H_,
                g_pph[kz], (my - 16) * 64, n0, kb, kb, 8);
}

// preduce: qs = ppq0+ppq1; hs = pph0+pph1  (393216 float4s -> 1536 blocks)
__global__ void __launch_bounds__(256) preduce_kernel()
{
    const int i4 = blockIdx.x * 256 + threadIdx.x;
    if (i4 < 131072) {
        const float4 a = reinterpret_cast<const float4*>(g_ppq[0])[i4];
        const float4 b = reinterpret_cast<const float4*>(g_ppq[1])[i4];
        reinterpret_cast<float4*>(g_qs)[i4] =
            make_float4(a.x + b.x, a.y + b.y, a.z + b.z, a.w + b.w);
    } else {
        const int j = i4 - 131072;
        const float4 a = reinterpret_cast<const float4*>(g_pph[0])[j];
        const float4 b = reinterpret_cast<const float4*>(g_pph[1])[j];
        reinterpret_cast<float4*>(g_hs)[j] =
            make_float4(a.x + b.x, a.y + b.y, a.z + b.z, a.w + b.w);
    }
}

// out: grid (8, 16, 4). kz<2 reads ctx, kz>=2 reads query (concat-aligned split-K).
__global__ void __launch_bounds__(256) out_wmma()
{
    __shared__ __align__(16) char smem[SMEM_BYTES];
    const int kz = blockIdx.z;
    const __nv_bfloat16* Ahi = (kz < 2) ? g_chi : g_qhi;
    const __nv_bfloat16* Alo = (kz < 2) ? g_clo : g_qlo;
    gemm_sk(smem, Ahi, Alo, g_wohi, g_wolo, 2 * H_,
            g_po[kz], blockIdx.y * 64, blockIdx.x * 64,
            (kz & 1) * 256, kz * 256, 8);
}

// oreduce: out = tanh(p0+p1+p2+p3 + bias)  (131072 float4s -> 512 blocks)
__global__ void __launch_bounds__(256) oreduce_kernel(
    const float* __restrict__ bias, float* __restrict__ out)
{
    const int i4 = blockIdx.x * 256 + threadIdx.x;
    const float4 p0 = reinterpret_cast<const float4*>(g_po[0])[i4];
    const float4 p1 = reinterpret_cast<const float4*>(g_po[1])[i4];
    const float4 p2 = reinterpret_cast<const float4*>(g_po[2])[i4];
    const float4 p3 = reinterpret_cast<const float4*>(g_po[3])[i4];
    const float4 bb = *reinterpret_cast<const float4*>(&bias[(i4 & 127) * 4]);
    float4 o;
    o.x = tanhf(p0.x + p1.x + p2.x + p3.x + bb.x);
    o.y = tanhf(p0.y + p1.y + p2.y + p3.y + bb.y);
    o.z = tanhf(p0.z + p1.z + p2.z + p3.z + bb.z);
    o.w = tanhf(p0.w + p1.w + p2.w + p3.w + bb.w);
    reinterpret_cast<float4*>(out)[i4] = o;
}

// ---------------------------------------------------------------------------
// Fused attention, 512 threads (16 warps): warp = (t_row, s_half).
// TT=8 t rows, SC=8 s rows per chunk; warp handles 4 chunk rows.
// Double-buffered pass1 (one sync per chunk). Pass2: 4 s-ranges + 2-round
// smem combine. ctx emitted as bf16 hi/lo.
// smem: 32KB + 8KB + 32B = 41KB (1 block/SM, 16 warps = 4/SMSP).
// ---------------------------------------------------------------------------
#define TT 8
#define SC 8

__global__ void __launch_bounds__(512) attn_kernel(
    const float* __restrict__ enc, const float* __restrict__ v,
    const int* __restrict__ lens)
{
    __shared__ float sh_hs[2][SC * H_];       // 32 KB double buffer
    __shared__ float sh_sc[TT][S_];           // 8 KB
    __shared__ float sh_rsum[TT];

    const int b     = blockIdx.y;
    const int t0    = blockIdx.x * TT;
    const int tid   = threadIdx.x;
    const int lane  = tid & 31;
    const int wid   = tid >> 5;               // 0..15
    const int t_loc = wid >> 1;               // 0..7
    const int shalf = wid & 1;                // 0..1

    const int len = lens[b];
    const int nch = (len + SC - 1) / SC;      // 16..32 chunks

    float qreg[16], vreg[16];
    {
        const float* qrow = g_qs + (size_t)(b * T_ + t0 + t_loc) * H_;
        #pragma unroll
        for (int j = 0; j < 16; j++) {
            qreg[j] = qrow[lane + 32 * j];
            vreg[j] = v[lane + 32 * j];
        }
    }

    const float* hsb  = g_hs + (size_t)b * S_ * H_;
    const float* encb = enc  + (size_t)b * S_ * H_;

    // ---- Pass 1: double-buffered (SC=8: 2 float4/thread), one sync/chunk ----
    float4 r[2];
    #pragma unroll
    for (int q = 0; q < 2; q++)
        r[q] = *reinterpret_cast<const float4*>(&hsb[(q * 512 + tid) * 4]);
    #pragma unroll
    for (int q = 0; q < 2; q++)
        *reinterpret_cast<float4*>(&sh_hs[0][(q * 512 + tid) * 4]) = r[q];

    #pragma unroll 1
    for (int it = 0; it < nch; ++it) {
        if (it + 1 < nch) {
            const float* nxt = &hsb[(size_t)(it + 1) * SC * H_];
            #pragma unroll
            for (int q = 0; q < 2; q++)
                r[q] = *reinterpret_cast<const float4*>(&nxt[(q * 512 + tid) * 4]);
        }
        __syncthreads();   // buf[it&1] ready; all warps done with buf[(it+1)&1]

        const float* base = sh_hs[it & 1];
        const int s0 = it * SC;
        #pragma unroll
        for (int i = 0; i < SC / 2; i++) {     // warp owns 4 of the 8 rows
            const int ro = shalf * (SC / 2) + i;
            const float* hrow = &base[ro * H_];
            float a0 = 0.f, a1 = 0.f;
            #pragma unroll
            for (int j = 0; j < 16; j += 2) {
                const float x0 = qreg[j] + hrow[lane + 32 * j];
                const float x1 = qreg[j + 1] + hrow[lane + 32 * (j + 1)];
                float t0f, t1f;
                asm("tanh.approx.f32 %0, %1;" : "=f"(t0f) : "f"(x0));
                asm("tanh.approx.f32 %0, %1;" : "=f"(t1f) : "f"(x1));
                a0 = fmaf(t0f, vreg[j], a0);
                a1 = fmaf(t1f, vreg[j + 1], a1);
            }
            float acc = a0 + a1;
            acc += __shfl_xor_sync(0xffffffffu, acc, 16);
            acc += __shfl_xor_sync(0xffffffffu, acc, 8);
            acc += __shfl_xor_sync(0xffffffffu, acc, 4);
            acc += __shfl_xor_sync(0xffffffffu, acc, 2);
            acc += __shfl_xor_sync(0xffffffffu, acc, 1);
            if (lane == 0) sh_sc[t_loc][s0 + ro] = acc;
        }

        if (it + 1 < nch) {
            float* dst = sh_hs[(it + 1) & 1];
            #pragma unroll
            for (int q = 0; q < 2; q++)
                *reinterpret_cast<float4*>(&dst[(q * 512 + tid) * 4]) = r[q];
        }
    }
    __syncthreads();

    // ---- Softmax (warps 0-7, one per t row) ----
    if (wid < TT) {
        const int t = wid;
        float vals[S_ / 32];
        float m = -1e30f;
        #pragma unroll
        for (int i = 0; i < S_ / 32; i++) {
            const int s = lane + 32 * i;
            const float sc = (s < len) ? sh_sc[t][s] : -1e30f;
            vals[i] = sc;
            m = fmaxf(m, sc);
        }
        #pragma unroll
        for (int o = 16; o; o >>= 1) m = fmaxf(m, __shfl_xor_sync(0xffffffffu, m, o));
        float sum = 0.f;
        #pragma unroll
        for (int i = 0; i < S_ / 32; i++) {
            const int s = lane + 32 * i;
            const float e = (s < len) ? __expf(vals[i] - m) : 0.f;
            sh_sc[t][s] = e;
            sum += e;
        }
        #pragma unroll
        for (int o = 16; o; o >>= 1) sum += __shfl_xor_sync(0xffffffffu, sum, o);
        if (lane == 0) sh_rsum[t] = 1.0f / sum;
    }
    __syncthreads();

    // ---- Pass 2: context; 4 groups over s-quarters of [0,len) ----
    const int g  = tid >> 7;                  // 0..3
    const int c4 = tid & 127;
    const int sbeg = (g * len) >> 2;
    const int send = ((g + 1) * len) >> 2;

    float4 acc4[TT];
    #pragma unroll
    for (int t = 0; t < TT; t++) acc4[t] = make_float4(0.f, 0.f, 0.f, 0.f);

    #pragma unroll 4
    for (int s = sbeg; s < send; s++) {
        const float4 e4 = *reinterpret_cast<const float4*>(&encb[(size_t)s * H_ + c4 * 4]);
        #pragma unroll
        for (int t = 0; t < TT; t++) {
            const float w = sh_sc[t][s];
            acc4[t].x = fmaf(w, e4.x, acc4[t].x);
            acc4[t].y = fmaf(w, e4.y, acc4[t].y);
            acc4[t].z = fmaf(w, e4.z, acc4[t].z);
            acc4[t].w = fmaf(w, e4.w, acc4[t].w);
        }
    }

    // combine: g1->bufA, g3->bufB; g0+=bufA, g2+=bufB then g2->bufB; g0+=bufB
    float* bufA = sh_hs[0];
    float* bufB = sh_hs[1];
    if (g == 1) {
        #pragma unroll
        for (int t = 0; t < TT; t++)
            *reinterpret_cast<float4*>(&bufA[(t * 128 + c4) * 4]) = acc4[t];
    }
    if (g == 3) {
        #pragma unroll
        for (int t = 0; t < TT; t++)
            *reinterpret_cast<float4*>(&bufB[(t * 128 + c4) * 4]) = acc4[t];
    }
    __syncthreads();
    if (g == 0) {
        #pragma unroll
        for (int t = 0; t < TT; t++) {
            const float4 p = *reinterpret_cast<const float4*>(&bufA[(t * 128 + c4) * 4]);
            acc4[t].x += p.x; acc4[t].y += p.y; acc4[t].z += p.z; acc4[t].w += p.w;
        }
    }
    if (g == 2) {
        #pragma unroll
        for (int t = 0; t < TT; t++) {
            const float4 p = *reinterpret_cast<const float4*>(&bufB[(t * 128 + c4) * 4]);
            acc4[t].x += p.x; acc4[t].y += p.y; acc4[t].z += p.z; acc4[t].w += p.w;
            *reinterpret_cast<float4*>(&bufB[(t * 128 + c4) * 4]) = acc4[t];
        }
    }
    __syncthreads();
    if (g == 0) {
        #pragma unroll
        for (int t = 0; t < TT; t++) {
            const float4 p = *reinterpret_cast<const float4*>(&bufB[(t * 128 + c4) * 4]);
            const float rs = sh_rsum[t];
            float4 o;
            o.x = (acc4[t].x + p.x) * rs;
            o.y = (acc4[t].y + p.y) * rs;
            o.z = (acc4[t].z + p.z) * rs;
            o.w = (acc4[t].w + p.w) * rs;
            union { __nv_bfloat16 h[4]; uint2 u; } ph, pl;
            bsplit(o.x, ph.h[0], pl.h[0]); bsplit(o.y, ph.h[1], pl.h[1]);
            bsplit(o.z, ph.h[2], pl.h[2]); bsplit(o.w, ph.h[3], pl.h[3]);
            const size_t off = (size_t)(b * T_ + t0 + t) * H_ + c4 * 4;
            *reinterpret_cast<uint2*>(&g_chi[off]) = ph.u;
            *reinterpret_cast<uint2*>(&g_clo[off]) = pl.u;
        }
    }
}

// ---------------------------------------------------------------------------
extern "C" void kernel_launch(void* const* d_in, const int* in_sizes, int n_in,
                              void* d_out, int out_size)
{
    const float* query = (const float*)d_in[0];
    const float* enc   = (const float*)d_in[1];
    const int*   lens  = (const int*)d_in[2];
    const float* W_s   = (const float*)d_in[3];
    const float* W_h   = (const float*)d_in[4];
    const float* v     = (const float*)d_in[5];
    const float* W_out = (const float*)d_in[6];
    const float* b_out = (const float*)d_in[7];
    float* out = (float*)d_out;

    convert_kernel<<<2560, 256>>>(query, enc, W_s, W_h, W_out);
    proj_wmma<<<dim3(8, 48, 2), 256>>>();
    preduce_kernel<<<1536, 256>>>();
    attn_kernel<<<dim3(T_ / TT, B_), 512>>>(enc, v, lens);
    out_wmma<<<dim3(8, 16, 4), 256>>>();
    oreduce_kernel<<<512, 256>>>(b_out, out);
}

// round 11
// speedup vs baseline: 1.2883x; 1.0357x over previous
#include <cuda_runtime.h>
#include <cuda_bf16.h>
#include <mma.h>
#include <math.h>
#include <stdint.h>

using namespace nvcuda;

#define B_ 8
#define T_ 128
#define S_ 256
#define H_ 512

// fp32 scratch
__device__ float g_qs[B_ * T_ * H_];                 // 2 MB
__device__ float g_hs[B_ * S_ * H_];                 // 4 MB
__device__ float g_ppq[2][B_ * T_ * H_];             // 4 MB  qs split-K partials
__device__ float g_pph[2][B_ * S_ * H_];             // 8 MB  hs split-K partials
__device__ float g_po[4][B_ * T_ * H_];              // 8 MB  out split-K partials
// bf16 hi/lo pre-split operands
__device__ __nv_bfloat16 g_qhi[B_ * T_ * H_],  g_qlo[B_ * T_ * H_];
__device__ __nv_bfloat16 g_ehi[B_ * S_ * H_],  g_elo[B_ * S_ * H_];
__device__ __nv_bfloat16 g_wshi[H_ * H_],      g_wslo[H_ * H_];
__device__ __nv_bfloat16 g_whhi[H_ * H_],      g_whlo[H_ * H_];
__device__ __nv_bfloat16 g_wohi[H_ * 2 * H_],  g_wolo[H_ * 2 * H_];
__device__ __nv_bfloat16 g_chi[B_ * T_ * H_],  g_clo[B_ * T_ * H_];

// ---------------------------------------------------------------------------
__device__ __forceinline__ void bsplit(float x, __nv_bfloat16& hi, __nv_bfloat16& lo) {
    hi = __float2bfloat16(x);
    lo = __float2bfloat16(x - __bfloat162float(hi));
}
__device__ __forceinline__ uint32_t smem_u32(const void* p) {
    uint32_t a;
    asm("{ .reg .u64 t; cvta.to.shared.u64 t, %1; cvt.u32.u64 %0, t; }"
        : "=r"(a) : "l"(p));
    return a;
}
__device__ __forceinline__ void cpa16(uint32_t d, const void* s) {
    asm volatile("cp.async.cg.shared.global [%0], [%1], 16;" :: "r"(d), "l"(s));
}
#define CP_COMMIT() asm volatile("cp.async.commit_group;" ::: "memory")
#define CP_WAIT1()  asm volatile("cp.async.wait_group 1;" ::: "memory")
#define CP_WAIT0()  asm volatile("cp.async.wait_group 0;" ::: "memory")

// ---------------------------------------------------------------------------
// convert: split inputs + weights into bf16 hi/lo (one float4 per thread)
// ---------------------------------------------------------------------------
__global__ void __launch_bounds__(256) convert_kernel(
    const float* __restrict__ query, const float* __restrict__ enc,
    const float* __restrict__ W_s, const float* __restrict__ W_h,
    const float* __restrict__ W_out)
{
    const int i4 = blockIdx.x * 256 + threadIdx.x;
    const float* src;
    __nv_bfloat16 *dhi, *dlo;
    int off;
    if (i4 < 131072)      { src = query; dhi = g_qhi;  dlo = g_qlo;  off = i4; }
    else if (i4 < 393216) { src = enc;   dhi = g_ehi;  dlo = g_elo;  off = i4 - 131072; }
    else if (i4 < 458752) { src = W_s;   dhi = g_wshi; dlo = g_wslo; off = i4 - 393216; }
    else if (i4 < 524288) { src = W_h;   dhi = g_whhi; dlo = g_whlo; off = i4 - 458752; }
    else                  { src = W_out; dhi = g_wohi; dlo = g_wolo; off = i4 - 524288; }

    const float4 v = reinterpret_cast<const float4*>(src)[off];
    union { __nv_bfloat16 h[4]; uint2 u; } ph, pl;
    bsplit(v.x, ph.h[0], pl.h[0]); bsplit(v.y, ph.h[1], pl.h[1]);
    bsplit(v.z, ph.h[2], pl.h[2]); bsplit(v.w, ph.h[3], pl.h[3]);
    reinterpret_cast<uint2*>(dhi)[off] = ph.u;
    reinterpret_cast<uint2*>(dlo)[off] = pl.u;
}

// ---------------------------------------------------------------------------
// Split-K wmma GEMM (bf16 3-term compensation), fp32 partial output.
// Tile 64x64, 256 threads, 8 warps (warp tile 16x32), K-chunk 32, 2-stage.
// ---------------------------------------------------------------------------
#define PITCH 40
#define TILE_B (64 * PITCH * 2)          // 5120 B
#define AHI_O 0
#define ALO_O (TILE_B)
#define BHI_O (2 * TILE_B)
#define BLO_O (3 * TILE_B)
#define BUF_B (4 * TILE_B)               // 20480 B per stage
#define SMEM_BYTES (2 * BUF_B)           // 40960 B

__device__ __forceinline__ void issue_chunk(
    uint32_t sb,
    const __nv_bfloat16* __restrict__ Ahi, const __nv_bfloat16* __restrict__ Alo,
    const __nv_bfloat16* __restrict__ Bhi, const __nv_bfloat16* __restrict__ Blo,
    int ldb, int m0, int n0, int aoff, int boff, int tid)
{
    const int row = tid >> 2, seg = tid & 3;       // 64 rows x 4 x 16B
    const uint32_t soff = (uint32_t)(row * (PITCH * 2) + seg * 16);
    const size_t ao = (size_t)(m0 + row) * H_ + aoff + seg * 8;
    const size_t bo = (size_t)(n0 + row) * ldb + boff + seg * 8;
    cpa16(sb + AHI_O + soff, Ahi + ao);
    cpa16(sb + ALO_O + soff, Alo + ao);
    cpa16(sb + BHI_O + soff, Bhi + bo);
    cpa16(sb + BLO_O + soff, Blo + bo);
}

__device__ __forceinline__ void gemm_sk(
    char* smem,
    const __nv_bfloat16* __restrict__ Ahi, const __nv_bfloat16* __restrict__ Alo,
    const __nv_bfloat16* __restrict__ Bhi, const __nv_bfloat16* __restrict__ Blo,
    int ldb, float* __restrict__ Cpart,
    int m0, int n0, int akbeg, int bkbeg, int nchunks)
{
    const int tid  = threadIdx.x;
    const int wid  = tid >> 5;
    const int m0w  = (wid >> 1) * 16;    // 4 m-warps x 16 rows
    const int n0w  = (wid & 1) * 32;     // 2 n-warps x 32 cols
    const uint32_t sb = smem_u32(smem);

    wmma::fragment<wmma::accumulator, 16, 16, 16, float> acc[2];
    wmma::fill_fragment(acc[0], 0.0f);
    wmma::fill_fragment(acc[1], 0.0f);

    issue_chunk(sb, Ahi, Alo, Bhi, Blo, ldb, m0, n0, akbeg, bkbeg, tid);
    CP_COMMIT();

    #pragma unroll 1
    for (int it = 0; it < nchunks; ++it) {
        if (it + 1 < nchunks) {
            issue_chunk(sb + ((it + 1) & 1) * BUF_B, Ahi, Alo, Bhi, Blo,
                        ldb, m0, n0, akbeg + (it + 1) * 32, bkbeg + (it + 1) * 32, tid);
            CP_COMMIT();
            CP_WAIT1();
        } else {
            CP_WAIT0();
        }
        __syncthreads();

        const char* buf = smem + (it & 1) * BUF_B;
        const __nv_bfloat16* sAhi = reinterpret_cast<const __nv_bfloat16*>(buf + AHI_O);
        const __nv_bfloat16* sAlo = reinterpret_cast<const __nv_bfloat16*>(buf + ALO_O);
        const __nv_bfloat16* sBhi = reinterpret_cast<const __nv_bfloat16*>(buf + BHI_O);
        const __nv_bfloat16* sBlo = reinterpret_cast<const __nv_bfloat16*>(buf + BLO_O);

        #pragma unroll
        for (int kf = 0; kf < 2; kf++) {
            const int ko = kf * 16;
            wmma::fragment<wmma::matrix_a, 16, 16, 16, __nv_bfloat16, wmma::row_major> ahi, alo;
            wmma::fragment<wmma::matrix_b, 16, 16, 16, __nv_bfloat16, wmma::col_major> bhi[2], blo[2];
            wmma::load_matrix_sync(ahi, &sAhi[m0w * PITCH + ko], PITCH);
            wmma::load_matrix_sync(alo, &sAlo[m0w * PITCH + ko], PITCH);
            #pragma unroll
            for (int ni = 0; ni < 2; ni++) {
                wmma::load_matrix_sync(bhi[ni], &sBhi[(n0w + 16 * ni) * PITCH + ko], PITCH);
                wmma::load_matrix_sync(blo[ni], &sBlo[(n0w + 16 * ni) * PITCH + ko], PITCH);
            }
            #pragma unroll
            for (int ni = 0; ni < 2; ni++) {
                wmma::mma_sync(acc[ni], ahi, bhi[ni], acc[ni]);
                wmma::mma_sync(acc[ni], ahi, blo[ni], acc[ni]);
                wmma::mma_sync(acc[ni], alo, bhi[ni], acc[ni]);
            }
        }
        __syncthreads();
    }

    #pragma unroll
    for (int ni = 0; ni < 2; ni++)
        wmma::store_matrix_sync(
            &Cpart[(size_t)(m0 + m0w) * H_ + n0 + n0w + 16 * ni],
            acc[ni], H_, wmma::mem_row_major);
}

// proj: grid (8, 48, 2). y<16 -> qs partial; else hs partial. kz splits K=512 in 2.
__global__ void __launch_bounds__(256) proj_wmma()
{
    __shared__ __align__(16) char smem[SMEM_BYTES];
    const int n0 = blockIdx.x * 64;
    const int my = blockIdx.y;
    const int kz = blockIdx.z;
    const int kb = kz * 256;
    if (my < 16)
        gemm_sk(smem, g_qhi, g_qlo, g_wshi, g_wslo, H_,
                g_ppq[kz], my * 64, n0, kb, kb, 8);
    else
        gemm_sk(smem, g_ehi, g_elo, g_whhi, g_whlo, H_,
                g_pph[kz], (my - 16) * 64, n0, kb, kb, 8);
}

// preduce: qs = ppq0+ppq1; hs = pph0+pph1  (393216 float4s -> 1536 blocks)
__global__ void __launch_bounds__(256) preduce_kernel()
{
    const int i4 = blockIdx.x * 256 + threadIdx.x;
    if (i4 < 131072) {
        const float4 a = reinterpret_cast<const float4*>(g_ppq[0])[i4];
        const float4 b = reinterpret_cast<const float4*>(g_ppq[1])[i4];
        reinterpret_cast<float4*>(g_qs)[i4] =
            make_float4(a.x + b.x, a.y + b.y, a.z + b.z, a.w + b.w);
    } else {
        const int j = i4 - 131072;
        const float4 a = reinterpret_cast<const float4*>(g_pph[0])[j];
        const float4 b = reinterpret_cast<const float4*>(g_pph[1])[j];
        reinterpret_cast<float4*>(g_hs)[j] =
            make_float4(a.x + b.x, a.y + b.y, a.z + b.z, a.w + b.w);
    }
}

// out: grid (8, 16, 4). kz<2 reads ctx, kz>=2 reads query (concat-aligned split-K).
__global__ void __launch_bounds__(256) out_wmma()
{
    __shared__ __align__(16) char smem[SMEM_BYTES];
    const int kz = blockIdx.z;
    const __nv_bfloat16* Ahi = (kz < 2) ? g_chi : g_qhi;
    const __nv_bfloat16* Alo = (kz < 2) ? g_clo : g_qlo;
    gemm_sk(smem, Ahi, Alo, g_wohi, g_wolo, 2 * H_,
            g_po[kz], blockIdx.y * 64, blockIdx.x * 64,
            (kz & 1) * 256, kz * 256, 8);
}

// oreduce: out = tanh(p0+p1+p2+p3 + bias)  (131072 float4s -> 512 blocks)
__global__ void __launch_bounds__(256) oreduce_kernel(
    const float* __restrict__ bias, float* __restrict__ out)
{
    const int i4 = blockIdx.x * 256 + threadIdx.x;
    const float4 p0 = reinterpret_cast<const float4*>(g_po[0])[i4];
    const float4 p1 = reinterpret_cast<const float4*>(g_po[1])[i4];
    const float4 p2 = reinterpret_cast<const float4*>(g_po[2])[i4];
    const float4 p3 = reinterpret_cast<const float4*>(g_po[3])[i4];
    const float4 bb = *reinterpret_cast<const float4*>(&bias[(i4 & 127) * 4]);
    float4 o;
    o.x = tanhf(p0.x + p1.x + p2.x + p3.x + bb.x);
    o.y = tanhf(p0.y + p1.y + p2.y + p3.y + bb.y);
    o.z = tanhf(p0.z + p1.z + p2.z + p3.z + bb.z);
    o.w = tanhf(p0.w + p1.w + p2.w + p3.w + bb.w);
    reinterpret_cast<float4*>(out)[i4] = o;
}

// ---------------------------------------------------------------------------
// Fused attention, TT=4, 512 threads, grid 256 blocks -> 2 CTAs/SM (32 warps).
// Warp = (t_row, s_quarter): 4 warps per t row, each owns 2 of 8 chunk rows.
// Double-buffered pass1 (one sync per chunk). Pass2: 4 s-ranges + 2-round
// smem combine. ctx emitted as bf16 hi/lo.
// smem: 32KB + 4KB + 16B = 36.2KB -> 2 blocks = 72.5KB/SM.
// ---------------------------------------------------------------------------
#define TT 4
#define SC 8

__global__ void __launch_bounds__(512, 2) attn_kernel(
    const float* __restrict__ enc, const float* __restrict__ v,
    const int* __restrict__ lens)
{
    __shared__ float sh_hs[2][SC * H_];       // 32 KB double buffer
    __shared__ float sh_sc[TT][S_];           // 4 KB
    __shared__ float sh_rsum[TT];

    const int b     = blockIdx.y;
    const int t0    = blockIdx.x * TT;
    const int tid   = threadIdx.x;
    const int lane  = tid & 31;
    const int wid   = tid >> 5;               // 0..15
    const int t_loc = wid >> 2;               // 0..3
    const int squad = wid & 3;                // 0..3

    const int len = lens[b];
    const int nch = (len + SC - 1) / SC;      // 16..32 chunks

    float qreg[16], vreg[16];
    {
        const float* qrow = g_qs + (size_t)(b * T_ + t0 + t_loc) * H_;
        #pragma unroll
        for (int j = 0; j < 16; j++) {
            qreg[j] = qrow[lane + 32 * j];
            vreg[j] = v[lane + 32 * j];
        }
    }

    const float* hsb  = g_hs + (size_t)b * S_ * H_;
    const float* encb = enc  + (size_t)b * S_ * H_;

    // ---- Pass 1: double-buffered (SC=8: 2 float4/thread), one sync/chunk ----
    float4 r[2];
    #pragma unroll
    for (int q = 0; q < 2; q++)
        r[q] = *reinterpret_cast<const float4*>(&hsb[(q * 512 + tid) * 4]);
    #pragma unroll
    for (int q = 0; q < 2; q++)
        *reinterpret_cast<float4*>(&sh_hs[0][(q * 512 + tid) * 4]) = r[q];

    #pragma unroll 1
    for (int it = 0; it < nch; ++it) {
        if (it + 1 < nch) {
            const float* nxt = &hsb[(size_t)(it + 1) * SC * H_];
            #pragma unroll
            for (int q = 0; q < 2; q++)
                r[q] = *reinterpret_cast<const float4*>(&nxt[(q * 512 + tid) * 4]);
        }
        __syncthreads();   // buf[it&1] ready; all warps done with buf[(it+1)&1]

        const float* base = sh_hs[it & 1];
        const int s0 = it * SC;
        #pragma unroll
        for (int i = 0; i < SC / 4; i++) {     // warp owns 2 of the 8 rows
            const int ro = squad * (SC / 4) + i;
            const float* hrow = &base[ro * H_];
            float a0 = 0.f, a1 = 0.f;
            #pragma unroll
            for (int j = 0; j < 16; j += 2) {
                const float x0 = qreg[j] + hrow[lane + 32 * j];
                const float x1 = qreg[j + 1] + hrow[lane + 32 * (j + 1)];
                float t0f, t1f;
                asm("tanh.approx.f32 %0, %1;" : "=f"(t0f) : "f"(x0));
                asm("tanh.approx.f32 %0, %1;" : "=f"(t1f) : "f"(x1));
                a0 = fmaf(t0f, vreg[j], a0);
                a1 = fmaf(t1f, vreg[j + 1], a1);
            }
            float acc = a0 + a1;
            acc += __shfl_xor_sync(0xffffffffu, acc, 16);
            acc += __shfl_xor_sync(0xffffffffu, acc, 8);
            acc += __shfl_xor_sync(0xffffffffu, acc, 4);
            acc += __shfl_xor_sync(0xffffffffu, acc, 2);
            acc += __shfl_xor_sync(0xffffffffu, acc, 1);
            if (lane == 0) sh_sc[t_loc][s0 + ro] = acc;
        }

        if (it + 1 < nch) {
            float* dst = sh_hs[(it + 1) & 1];
            #pragma unroll
            for (int q = 0; q < 2; q++)
                *reinterpret_cast<float4*>(&dst[(q * 512 + tid) * 4]) = r[q];
        }
    }
    __syncthreads();

    // ---- Softmax (warps 0-3, one per t row) ----
    if (wid < TT) {
        const int t = wid;
        float vals[S_ / 32];
        float m = -1e30f;
        #pragma unroll
        for (int i = 0; i < S_ / 32; i++) {
            const int s = lane + 32 * i;
            const float sc = (s < len) ? sh_sc[t][s] : -1e30f;
            vals[i] = sc;
            m = fmaxf(m, sc);
        }
        #pragma unroll
        for (int o = 16; o; o >>= 1) m = fmaxf(m, __shfl_xor_sync(0xffffffffu, m, o));
        float sum = 0.f;
        #pragma unroll
        for (int i = 0; i < S_ / 32; i++) {
            const int s = lane + 32 * i;
            const float e = (s < len) ? __expf(vals[i] - m) : 0.f;
            sh_sc[t][s] = e;
            sum += e;
        }
        #pragma unroll
        for (int o = 16; o; o >>= 1) sum += __shfl_xor_sync(0xffffffffu, sum, o);
        if (lane == 0) sh_rsum[t] = 1.0f / sum;
    }
    __syncthreads();

    // ---- Pass 2: context; 4 groups over s-quarters of [0,len) ----
    const int g  = tid >> 7;                  // 0..3
    const int c4 = tid & 127;
    const int sbeg = (g * len) >> 2;
    const int send = ((g + 1) * len) >> 2;

    float4 acc4[TT];
    #pragma unroll
    for (int t = 0; t < TT; t++) acc4[t] = make_float4(0.f, 0.f, 0.f, 0.f);

    #pragma unroll 4
    for (int s = sbeg; s < send; s++) {
        const float4 e4 = *reinterpret_cast<const float4*>(&encb[(size_t)s * H_ + c4 * 4]);
        #pragma unroll
        for (int t = 0; t < TT; t++) {
            const float w = sh_sc[t][s];
            acc4[t].x = fmaf(w, e4.x, acc4[t].x);
            acc4[t].y = fmaf(w, e4.y, acc4[t].y);
            acc4[t].z = fmaf(w, e4.z, acc4[t].z);
            acc4[t].w = fmaf(w, e4.w, acc4[t].w);
        }
    }

    // combine: g1->bufA, g3->bufB; g0+=bufA, g2+=bufB then g2->bufB; g0+=bufB
    float* bufA = sh_hs[0];
    float* bufB = sh_hs[1];
    if (g == 1) {
        #pragma unroll
        for (int t = 0; t < TT; t++)
            *reinterpret_cast<float4*>(&bufA[(t * 128 + c4) * 4]) = acc4[t];
    }
    if (g == 3) {
        #pragma unroll
        for (int t = 0; t < TT; t++)
            *reinterpret_cast<float4*>(&bufB[(t * 128 + c4) * 4]) = acc4[t];
    }
    __syncthreads();
    if (g == 0) {
        #pragma unroll
        for (int t = 0; t < TT; t++) {
            const float4 p = *reinterpret_cast<const float4*>(&bufA[(t * 128 + c4) * 4]);
            acc4[t].x += p.x; acc4[t].y += p.y; acc4[t].z += p.z; acc4[t].w += p.w;
        }
    }
    if (g == 2) {
        #pragma unroll
        for (int t = 0; t < TT; t++) {
            const float4 p = *reinterpret_cast<const float4*>(&bufB[(t * 128 + c4) * 4]);
            acc4[t].x += p.x; acc4[t].y += p.y; acc4[t].z += p.z; acc4[t].w += p.w;
            *reinterpret_cast<float4*>(&bufB[(t * 128 + c4) * 4]) = acc4[t];
        }
    }
    __syncthreads();
    if (g == 0) {
        #pragma unroll
        for (int t = 0; t < TT; t++) {
            const float4 p = *reinterpret_cast<const float4*>(&bufB[(t * 128 + c4) * 4]);
            const float rs = sh_rsum[t];
            float4 o;
            o.x = (acc4[t].x + p.x) * rs;
            o.y = (acc4[t].y + p.y) * rs;
            o.z = (acc4[t].z + p.z) * rs;
            o.w = (acc4[t].w + p.w) * rs;
            union { __nv_bfloat16 h[4]; uint2 u; } ph, pl;
            bsplit(o.x, ph.h[0], pl.h[0]); bsplit(o.y, ph.h[1], pl.h[1]);
            bsplit(o.z, ph.h[2], pl.h[2]); bsplit(o.w, ph.h[3], pl.h[3]);
            const size_t off = (size_t)(b * T_ + t0 + t) * H_ + c4 * 4;
            *reinterpret_cast<uint2*>(&g_chi[off]) = ph.u;
            *reinterpret_cast<uint2*>(&g_clo[off]) = pl.u;
        }
    }
}

// ---------------------------------------------------------------------------
extern "C" void kernel_launch(void* const* d_in, const int* in_sizes, int n_in,
                              void* d_out, int out_size)
{
    const float* query = (const float*)d_in[0];
    const float* enc   = (const float*)d_in[1];
    const int*   lens  = (const int*)d_in[2];
    const float* W_s   = (const float*)d_in[3];
    const float* W_h   = (const float*)d_in[4];
    const float* v     = (const float*)d_in[5];
    const float* W_out = (const float*)d_in[6];
    const float* b_out = (const float*)d_in[7];
    float* out = (float*)d_out;

    convert_kernel<<<2560, 256>>>(query, enc, W_s, W_h, W_out);
    proj_wmma<<<dim3(8, 48, 2), 256>>>();
    preduce_kernel<<<1536, 256>>>();
    attn_kernel<<<dim3(T_ / TT, B_), 512>>>(enc, v, lens);
    out_wmma<<<dim3(8, 16, 4), 256>>>();
    oreduce_kernel<<<512, 256>>>(b_out, out);
}

// round 12
// speedup vs baseline: 1.3348x; 1.0361x over previous
#include <cuda_runtime.h>
#include <cuda_bf16.h>
#include <mma.h>
#include <math.h>
#include <stdint.h>

using namespace nvcuda;

#define B_ 8
#define T_ 128
#define S_ 256
#define H_ 512

// fp32 scratch
__device__ float g_hs[B_ * S_ * H_];                 // 4 MB
__device__ float g_ppq[2][B_ * T_ * H_];             // 4 MB  qs split-K partials
__device__ float g_pph[2][B_ * S_ * H_];             // 8 MB  hs split-K partials
__device__ float g_po[4][B_ * T_ * H_];              // 8 MB  out split-K partials
// bf16 hi/lo pre-split operands
__device__ __nv_bfloat16 g_qhi[B_ * T_ * H_],  g_qlo[B_ * T_ * H_];
__device__ __nv_bfloat16 g_ehi[B_ * S_ * H_],  g_elo[B_ * S_ * H_];
__device__ __nv_bfloat16 g_wshi[H_ * H_],      g_wslo[H_ * H_];
__device__ __nv_bfloat16 g_whhi[H_ * H_],      g_whlo[H_ * H_];
__device__ __nv_bfloat16 g_wohi[H_ * 2 * H_],  g_wolo[H_ * 2 * H_];
__device__ __nv_bfloat16 g_chi[B_ * T_ * H_],  g_clo[B_ * T_ * H_];

// ---------------------------------------------------------------------------
__device__ __forceinline__ void bsplit(float x, __nv_bfloat16& hi, __nv_bfloat16& lo) {
    hi = __float2bfloat16(x);
    lo = __float2bfloat16(x - __bfloat162float(hi));
}
__device__ __forceinline__ uint32_t smem_u32(const void* p) {
    uint32_t a;
    asm("{ .reg .u64 t; cvta.to.shared.u64 t, %1; cvt.u32.u64 %0, t; }"
        : "=r"(a) : "l"(p));
    return a;
}
__device__ __forceinline__ void cpa16(uint32_t d, const void* s) {
    asm volatile("cp.async.cg.shared.global [%0], [%1], 16;" :: "r"(d), "l"(s));
}
#define CP_COMMIT() asm volatile("cp.async.commit_group;" ::: "memory")
#define CP_WAIT1()  asm volatile("cp.async.wait_group 1;" ::: "memory")
#define CP_WAIT0()  asm volatile("cp.async.wait_group 0;" ::: "memory")

// ---------------------------------------------------------------------------
// convert: split inputs + weights into bf16 hi/lo (one float4 per thread)
// ---------------------------------------------------------------------------
__global__ void __launch_bounds__(256) convert_kernel(
    const float* __restrict__ query, const float* __restrict__ enc,
    const float* __restrict__ W_s, const float* __restrict__ W_h,
    const float* __restrict__ W_out)
{
    const int i4 = blockIdx.x * 256 + threadIdx.x;
    const float* src;
    __nv_bfloat16 *dhi, *dlo;
    int off;
    if (i4 < 131072)      { src = query; dhi = g_qhi;  dlo = g_qlo;  off = i4; }
    else if (i4 < 393216) { src = enc;   dhi = g_ehi;  dlo = g_elo;  off = i4 - 131072; }
    else if (i4 < 458752) { src = W_s;   dhi = g_wshi; dlo = g_wslo; off = i4 - 393216; }
    else if (i4 < 524288) { src = W_h;   dhi = g_whhi; dlo = g_whlo; off = i4 - 458752; }
    else                  { src = W_out; dhi = g_wohi; dlo = g_wolo; off = i4 - 524288; }

    const float4 v = reinterpret_cast<const float4*>(src)[off];
    union { __nv_bfloat16 h[4]; uint2 u; } ph, pl;
    bsplit(v.x, ph.h[0], pl.h[0]); bsplit(v.y, ph.h[1], pl.h[1]);
    bsplit(v.z, ph.h[2], pl.h[2]); bsplit(v.w, ph.h[3], pl.h[3]);
    reinterpret_cast<uint2*>(dhi)[off] = ph.u;
    reinterpret_cast<uint2*>(dlo)[off] = pl.u;
}

// ---------------------------------------------------------------------------
// Split-K wmma GEMM (bf16 3-term compensation), fp32 partial output.
// Tile 64x64, 256 threads, 8 warps (warp tile 16x32), K-chunk 32, 2-stage.
// ---------------------------------------------------------------------------
#define PITCH 40
#define TILE_B (64 * PITCH * 2)          // 5120 B
#define AHI_O 0
#define ALO_O (TILE_B)
#define BHI_O (2 * TILE_B)
#define BLO_O (3 * TILE_B)
#define BUF_B (4 * TILE_B)               // 20480 B per stage
#define SMEM_BYTES (2 * BUF_B)           // 40960 B

__device__ __forceinline__ void issue_chunk(
    uint32_t sb,
    const __nv_bfloat16* __restrict__ Ahi, const __nv_bfloat16* __restrict__ Alo,
    const __nv_bfloat16* __restrict__ Bhi, const __nv_bfloat16* __restrict__ Blo,
    int ldb, int m0, int n0, int aoff, int boff, int tid)
{
    const int row = tid >> 2, seg = tid & 3;       // 64 rows x 4 x 16B
    const uint32_t soff = (uint32_t)(row * (PITCH * 2) + seg * 16);
    const size_t ao = (size_t)(m0 + row) * H_ + aoff + seg * 8;
    const size_t bo = (size_t)(n0 + row) * ldb + boff + seg * 8;
    cpa16(sb + AHI_O + soff, Ahi + ao);
    cpa16(sb + ALO_O + soff, Alo + ao);
    cpa16(sb + BHI_O + soff, Bhi + bo);
    cpa16(sb + BLO_O + soff, Blo + bo);
}

__device__ __forceinline__ void gemm_sk(
    char* smem,
    const __nv_bfloat16* __restrict__ Ahi, const __nv_bfloat16* __restrict__ Alo,
    const __nv_bfloat16* __restrict__ Bhi, const __nv_bfloat16* __restrict__ Blo,
    int ldb, float* __restrict__ Cpart,
    int m0, int n0, int akbeg, int bkbeg, int nchunks)
{
    const int tid  = threadIdx.x;
    const int wid  = tid >> 5;
    const int m0w  = (wid >> 1) * 16;    // 4 m-warps x 16 rows
    const int n0w  = (wid & 1) * 32;     // 2 n-warps x 32 cols
    const uint32_t sb = smem_u32(smem);

    wmma::fragment<wmma::accumulator, 16, 16, 16, float> acc[2];
    wmma::fill_fragment(acc[0], 0.0f);
    wmma::fill_fragment(acc[1], 0.0f);

    issue_chunk(sb, Ahi, Alo, Bhi, Blo, ldb, m0, n0, akbeg, bkbeg, tid);
    CP_COMMIT();

    #pragma unroll 1
    for (int it = 0; it < nchunks; ++it) {
        if (it + 1 < nchunks) {
            issue_chunk(sb + ((it + 1) & 1) * BUF_B, Ahi, Alo, Bhi, Blo,
                        ldb, m0, n0, akbeg + (it + 1) * 32, bkbeg + (it + 1) * 32, tid);
            CP_COMMIT();
            CP_WAIT1();
        } else {
            CP_WAIT0();
        }
        __syncthreads();

        const char* buf = smem + (it & 1) * BUF_B;
        const __nv_bfloat16* sAhi = reinterpret_cast<const __nv_bfloat16*>(buf + AHI_O);
        const __nv_bfloat16* sAlo = reinterpret_cast<const __nv_bfloat16*>(buf + ALO_O);
        const __nv_bfloat16* sBhi = reinterpret_cast<const __nv_bfloat16*>(buf + BHI_O);
        const __nv_bfloat16* sBlo = reinterpret_cast<const __nv_bfloat16*>(buf + BLO_O);

        #pragma unroll
        for (int kf = 0; kf < 2; kf++) {
            const int ko = kf * 16;
            wmma::fragment<wmma::matrix_a, 16, 16, 16, __nv_bfloat16, wmma::row_major> ahi, alo;
            wmma::fragment<wmma::matrix_b, 16, 16, 16, __nv_bfloat16, wmma::col_major> bhi[2], blo[2];
            wmma::load_matrix_sync(ahi, &sAhi[m0w * PITCH + ko], PITCH);
            wmma::load_matrix_sync(alo, &sAlo[m0w * PITCH + ko], PITCH);
            #pragma unroll
            for (int ni = 0; ni < 2; ni++) {
                wmma::load_matrix_sync(bhi[ni], &sBhi[(n0w + 16 * ni) * PITCH + ko], PITCH);
                wmma::load_matrix_sync(blo[ni], &sBlo[(n0w + 16 * ni) * PITCH + ko], PITCH);
            }
            #pragma unroll
            for (int ni = 0; ni < 2; ni++) {
                wmma::mma_sync(acc[ni], ahi, bhi[ni], acc[ni]);
                wmma::mma_sync(acc[ni], ahi, blo[ni], acc[ni]);
                wmma::mma_sync(acc[ni], alo, bhi[ni], acc[ni]);
            }
        }
        __syncthreads();
    }

    #pragma unroll
    for (int ni = 0; ni < 2; ni++)
        wmma::store_matrix_sync(
            &Cpart[(size_t)(m0 + m0w) * H_ + n0 + n0w + 16 * ni],
            acc[ni], H_, wmma::mem_row_major);
}

// proj: grid (8, 48, 2). y<16 -> qs partial; else hs partial. kz splits K=512 in 2.
__global__ void __launch_bounds__(256) proj_wmma()
{
    __shared__ __align__(16) char smem[SMEM_BYTES];
    const int n0 = blockIdx.x * 64;
    const int my = blockIdx.y;
    const int kz = blockIdx.z;
    const int kb = kz * 256;
    if (my < 16)
        gemm_sk(smem, g_qhi, g_qlo, g_wshi, g_wslo, H_,
                g_ppq[kz], my * 64, n0, kb, kb, 8);
    else
        gemm_sk(smem, g_ehi, g_elo, g_whhi, g_whlo, H_,
                g_pph[kz], (my - 16) * 64, n0, kb, kb, 8);
}

// preduce (hs only): hs = pph0+pph1  (262144 float4s -> 1024 blocks)
__global__ void __launch_bounds__(256) preduce_kernel()
{
    const int j = blockIdx.x * 256 + threadIdx.x;
    const float4 a = reinterpret_cast<const float4*>(g_pph[0])[j];
    const float4 b = reinterpret_cast<const float4*>(g_pph[1])[j];
    reinterpret_cast<float4*>(g_hs)[j] =
        make_float4(a.x + b.x, a.y + b.y, a.z + b.z, a.w + b.w);
}

// out: grid (8, 16, 4). kz<2 reads ctx, kz>=2 reads query (concat-aligned split-K).
__global__ void __launch_bounds__(256) out_wmma()
{
    __shared__ __align__(16) char smem[SMEM_BYTES];
    const int kz = blockIdx.z;
    const __nv_bfloat16* Ahi = (kz < 2) ? g_chi : g_qhi;
    const __nv_bfloat16* Alo = (kz < 2) ? g_clo : g_qlo;
    gemm_sk(smem, Ahi, Alo, g_wohi, g_wolo, 2 * H_,
            g_po[kz], blockIdx.y * 64, blockIdx.x * 64,
            (kz & 1) * 256, kz * 256, 8);
}

// oreduce: out = tanh(p0+p1+p2+p3 + bias)  (131072 float4s -> 512 blocks)
__global__ void __launch_bounds__(256) oreduce_kernel(
    const float* __restrict__ bias, float* __restrict__ out)
{
    const int i4 = blockIdx.x * 256 + threadIdx.x;
    const float4 p0 = reinterpret_cast<const float4*>(g_po[0])[i4];
    const float4 p1 = reinterpret_cast<const float4*>(g_po[1])[i4];
    const float4 p2 = reinterpret_cast<const float4*>(g_po[2])[i4];
    const float4 p3 = reinterpret_cast<const float4*>(g_po[3])[i4];
    const float4 bb = *reinterpret_cast<const float4*>(&bias[(i4 & 127) * 4]);
    float4 o;
    o.x = tanhf(p0.x + p1.x + p2.x + p3.x + bb.x);
    o.y = tanhf(p0.y + p1.y + p2.y + p3.y + bb.y);
    o.z = tanhf(p0.z + p1.z + p2.z + p3.z + bb.z);
    o.w = tanhf(p0.w + p1.w + p2.w + p3.w + bb.w);
    reinterpret_cast<float4*>(out)[i4] = o;
}

// ---------------------------------------------------------------------------
// Fused attention, TT=4, 512 threads, 256 blocks, 2 CTAs/SM.
// Vectorized pass1: per-thread h-chunk mapping h = c*128 + lane*4 + e
// (dot product permutation-invariant), 4x LDS.128 per row (conflict-free).
// qreg fuses the qs split-K partial add. Scores stored transposed [S][TT]
// so pass2 reads all 4 t-weights with one LDS.128 broadcast.
// ---------------------------------------------------------------------------
#define TT 4
#define SC 8

__global__ void __launch_bounds__(512, 2) attn_kernel(
    const float* __restrict__ enc, const float* __restrict__ v,
    const int* __restrict__ lens)
{
    __shared__ float sh_hs[2][SC * H_];       // 32 KB double buffer
    __shared__ float sh_sc[S_][TT];           // 4 KB (transposed)
    __shared__ float sh_rsum[TT];

    const int b     = blockIdx.y;
    const int t0    = blockIdx.x * TT;
    const int tid   = threadIdx.x;
    const int lane  = tid & 31;
    const int wid   = tid >> 5;               // 0..15
    const int t_loc = wid >> 2;               // 0..3
    const int squad = wid & 3;                // 0..3

    const int len = lens[b];
    const int nch = (len + SC - 1) / SC;      // 16..32 chunks

    // q (sum of split-K partials) + v in float4s, mapping h = c*128 + lane*4
    float4 q4[4], v4[4];
    {
        const size_t ro = (size_t)(b * T_ + t0 + t_loc) * H_;
        #pragma unroll
        for (int c = 0; c < 4; c++) {
            const int off = c * 128 + lane * 4;
            const float4 p0 = *reinterpret_cast<const float4*>(&g_ppq[0][ro + off]);
            const float4 p1 = *reinterpret_cast<const float4*>(&g_ppq[1][ro + off]);
            q4[c] = make_float4(p0.x + p1.x, p0.y + p1.y, p0.z + p1.z, p0.w + p1.w);
            v4[c] = *reinterpret_cast<const float4*>(&v[off]);
        }
    }

    const float* hsb  = g_hs + (size_t)b * S_ * H_;
    const float* encb = enc  + (size_t)b * S_ * H_;

    // ---- Pass 1: double-buffered (SC=8: 2 float4/thread), one sync/chunk ----
    float4 r[2];
    #pragma unroll
    for (int q = 0; q < 2; q++)
        r[q] = *reinterpret_cast<const float4*>(&hsb[(q * 512 + tid) * 4]);
    #pragma unroll
    for (int q = 0; q < 2; q++)
        *reinterpret_cast<float4*>(&sh_hs[0][(q * 512 + tid) * 4]) = r[q];

    #pragma unroll 1
    for (int it = 0; it < nch; ++it) {
        if (it + 1 < nch) {
            const float* nxt = &hsb[(size_t)(it + 1) * SC * H_];
            #pragma unroll
            for (int q = 0; q < 2; q++)
                r[q] = *reinterpret_cast<const float4*>(&nxt[(q * 512 + tid) * 4]);
        }
        __syncthreads();   // buf[it&1] ready; all warps done with buf[(it+1)&1]

        const float* base = sh_hs[it & 1];
        const int s0 = it * SC;
        #pragma unroll
        for (int i = 0; i < SC / 4; i++) {     // warp owns 2 of the 8 rows
            const int ro = squad * (SC / 4) + i;
            const float4* hrow4 = reinterpret_cast<const float4*>(&base[ro * H_]);
            float a0 = 0.f, a1 = 0.f;
            #pragma unroll
            for (int c = 0; c < 4; c++) {
                const float4 h4 = hrow4[c * 32 + lane];
                float tx, ty, tz, tw;
                asm("tanh.approx.f32 %0, %1;" : "=f"(tx) : "f"(q4[c].x + h4.x));
                asm("tanh.approx.f32 %0, %1;" : "=f"(ty) : "f"(q4[c].y + h4.y));
                asm("tanh.approx.f32 %0, %1;" : "=f"(tz) : "f"(q4[c].z + h4.z));
                asm("tanh.approx.f32 %0, %1;" : "=f"(tw) : "f"(q4[c].w + h4.w));
                a0 = fmaf(tx, v4[c].x, a0);
                a1 = fmaf(ty, v4[c].y, a1);
                a0 = fmaf(tz, v4[c].z, a0);
                a1 = fmaf(tw, v4[c].w, a1);
            }
            float acc = a0 + a1;
            acc += __shfl_xor_sync(0xffffffffu, acc, 16);
            acc += __shfl_xor_sync(0xffffffffu, acc, 8);
            acc += __shfl_xor_sync(0xffffffffu, acc, 4);
            acc += __shfl_xor_sync(0xffffffffu, acc, 2);
            acc += __shfl_xor_sync(0xffffffffu, acc, 1);
            if (lane == 0) sh_sc[s0 + ro][t_loc] = acc;
        }

        if (it + 1 < nch) {
            float* dst = sh_hs[(it + 1) & 1];
            #pragma unroll
            for (int q = 0; q < 2; q++)
                *reinterpret_cast<float4*>(&dst[(q * 512 + tid) * 4]) = r[q];
        }
    }
    __syncthreads();

    // ---- Softmax (warps 0-3, one per t row) ----
    if (wid < TT) {
        const int t = wid;
        float vals[S_ / 32];
        float m = -1e30f;
        #pragma unroll
        for (int i = 0; i < S_ / 32; i++) {
            const int s = lane + 32 * i;
            const float sc = (s < len) ? sh_sc[s][t] : -1e30f;
            vals[i] = sc;
            m = fmaxf(m, sc);
        }
        #pragma unroll
        for (int o = 16; o; o >>= 1) m = fmaxf(m, __shfl_xor_sync(0xffffffffu, m, o));
        float sum = 0.f;
        #pragma unroll
        for (int i = 0; i < S_ / 32; i++) {
            const int s = lane + 32 * i;
            const float e = (s < len) ? __expf(vals[i] - m) : 0.f;
            sh_sc[s][t] = e;
            sum += e;
        }
        #pragma unroll
        for (int o = 16; o; o >>= 1) sum += __shfl_xor_sync(0xffffffffu, sum, o);
        if (lane == 0) sh_rsum[t] = 1.0f / sum;
    }
    __syncthreads();

    // ---- Pass 2: context; 4 groups over s-quarters of [0,len) ----
    const int g  = tid >> 7;                  // 0..3
    const int c4 = tid & 127;
    const int sbeg = (g * len) >> 2;
    const int send = ((g + 1) * len) >> 2;

    float4 acc4[TT];
    #pragma unroll
    for (int t = 0; t < TT; t++) acc4[t] = make_float4(0.f, 0.f, 0.f, 0.f);

    #pragma unroll 4
    for (int s = sbeg; s < send; s++) {
        const float4 e4 = *reinterpret_cast<const float4*>(&encb[(size_t)s * H_ + c4 * 4]);
        const float4 w4 = *reinterpret_cast<const float4*>(&sh_sc[s][0]);
        acc4[0].x = fmaf(w4.x, e4.x, acc4[0].x);
        acc4[0].y = fmaf(w4.x, e4.y, acc4[0].y);
        acc4[0].z = fmaf(w4.x, e4.z, acc4[0].z);
        acc4[0].w = fmaf(w4.x, e4.w, acc4[0].w);
        acc4[1].x = fmaf(w4.y, e4.x, acc4[1].x);
        acc4[1].y = fmaf(w4.y, e4.y, acc4[1].y);
        acc4[1].z = fmaf(w4.y, e4.z, acc4[1].z);
        acc4[1].w = fmaf(w4.y, e4.w, acc4[1].w);
        acc4[2].x = fmaf(w4.z, e4.x, acc4[2].x);
        acc4[2].y = fmaf(w4.z, e4.y, acc4[2].y);
        acc4[2].z = fmaf(w4.z, e4.z, acc4[2].z);
        acc4[2].w = fmaf(w4.z, e4.w, acc4[2].w);
        acc4[3].x = fmaf(w4.w, e4.x, acc4[3].x);
        acc4[3].y = fmaf(w4.w, e4.y, acc4[3].y);
        acc4[3].z = fmaf(w4.w, e4.z, acc4[3].z);
        acc4[3].w = fmaf(w4.w, e4.w, acc4[3].w);
    }

    // combine: g1->bufA, g3->bufB; g0+=bufA, g2+=bufB then g2->bufB; g0+=bufB
    float* bufA = sh_hs[0];
    float* bufB = sh_hs[1];
    if (g == 1) {
        #pragma unroll
        for (int t = 0; t < TT; t++)
            *reinterpret_cast<float4*>(&bufA[(t * 128 + c4) * 4]) = acc4[t];
    }
    if (g == 3) {
        #pragma unroll
        for (int t = 0; t < TT; t++)
            *reinterpret_cast<float4*>(&bufB[(t * 128 + c4) * 4]) = acc4[t];
    }
    __syncthreads();
    if (g == 0) {
        #pragma unroll
        for (int t = 0; t < TT; t++) {
            const float4 p = *reinterpret_cast<const float4*>(&bufA[(t * 128 + c4) * 4]);
            acc4[t].x += p.x; acc4[t].y += p.y; acc4[t].z += p.z; acc4[t].w += p.w;
        }
    }
    if (g == 2) {
        #pragma unroll
        for (int t = 0; t < TT; t++) {
            const float4 p = *reinterpret_cast<const float4*>(&bufB[(t * 128 + c4) * 4]);
            acc4[t].x += p.x; acc4[t].y += p.y; acc4[t].z += p.z; acc4[t].w += p.w;
            *reinterpret_cast<float4*>(&bufB[(t * 128 + c4) * 4]) = acc4[t];
        }
    }
    __syncthreads();
    if (g == 0) {
        #pragma unroll
        for (int t = 0; t < TT; t++) {
            const float4 p = *reinterpret_cast<const float4*>(&bufB[(t * 128 + c4) * 4]);
            const float rs = sh_rsum[t];
            float4 o;
            o.x = (acc4[t].x + p.x) * rs;
            o.y = (acc4[t].y + p.y) * rs;
            o.z = (acc4[t].z + p.z) * rs;
            o.w = (acc4[t].w + p.w) * rs;
            union { __nv_bfloat16 h[4]; uint2 u; } ph, pl;
            bsplit(o.x, ph.h[0], pl.h[0]); bsplit(o.y, ph.h[1], pl.h[1]);
            bsplit(o.z, ph.h[2], pl.h[2]); bsplit(o.w, ph.h[3], pl.h[3]);
            const size_t off = (size_t)(b * T_ + t0 + t) * H_ + c4 * 4;
            *reinterpret_cast<uint2*>(&g_chi[off]) = ph.u;
            *reinterpret_cast<uint2*>(&g_clo[off]) = pl.u;
        }
    }
}

// ---------------------------------------------------------------------------
extern "C" void kernel_launch(void* const* d_in, const int* in_sizes, int n_in,
                              void* d_out, int out_size)
{
    const float* query = (const float*)d_in[0];
    const float* enc   = (const float*)d_in[1];
    const int*   lens  = (const int*)d_in[2];
    const float* W_s   = (const float*)d_in[3];
    const float* W_h   = (const float*)d_in[4];
    const float* v     = (const float*)d_in[5];
    const float* W_out = (const float*)d_in[6];
    const float* b_out = (const float*)d_in[7];
    float* out = (float*)d_out;

    convert_kernel<<<2560, 256>>>(query, enc, W_s, W_h, W_out);
    proj_wmma<<<dim3(8, 48, 2), 256>>>();
    preduce_kernel<<<1024, 256>>>();
    attn_kernel<<<dim3(T_ / TT, B_), 512>>>(enc, v, lens);
    out_wmma<<<dim3(8, 16, 4), 256>>>();
    oreduce_kernel<<<512, 256>>>(b_out, out);
}

// round 13
// speedup vs baseline: 1.3847x; 1.0374x over previous
#include <cuda_runtime.h>
#include <cuda_bf16.h>
#include <cuda_fp16.h>
#include <mma.h>
#include <math.h>
#include <stdint.h>

using namespace nvcuda;

#define B_ 8
#define T_ 128
#define S_ 256
#define H_ 512

// scratch
__device__ __half g_hsh[B_ * S_ * H_];               // 2 MB  hs in fp16
__device__ float g_ppq[2][B_ * T_ * H_];             // 4 MB  qs split-K partials
__device__ float g_pph[2][B_ * S_ * H_];             // 8 MB  hs split-K partials
__device__ float g_po[4][B_ * T_ * H_];              // 8 MB  out split-K partials
// bf16 hi/lo pre-split operands
__device__ __nv_bfloat16 g_qhi[B_ * T_ * H_],  g_qlo[B_ * T_ * H_];
__device__ __nv_bfloat16 g_ehi[B_ * S_ * H_],  g_elo[B_ * S_ * H_];
__device__ __nv_bfloat16 g_wshi[H_ * H_],      g_wslo[H_ * H_];
__device__ __nv_bfloat16 g_whhi[H_ * H_],      g_whlo[H_ * H_];
__device__ __nv_bfloat16 g_wohi[H_ * 2 * H_],  g_wolo[H_ * 2 * H_];
__device__ __nv_bfloat16 g_chi[B_ * T_ * H_],  g_clo[B_ * T_ * H_];

// ---------------------------------------------------------------------------
__device__ __forceinline__ void bsplit(float x, __nv_bfloat16& hi, __nv_bfloat16& lo) {
    hi = __float2bfloat16(x);
    lo = __float2bfloat16(x - __bfloat162float(hi));
}
__device__ __forceinline__ uint32_t smem_u32(const void* p) {
    uint32_t a;
    asm("{ .reg .u64 t; cvta.to.shared.u64 t, %1; cvt.u32.u64 %0, t; }"
        : "=r"(a) : "l"(p));
    return a;
}
__device__ __forceinline__ void cpa16(uint32_t d, const void* s) {
    asm volatile("cp.async.cg.shared.global [%0], [%1], 16;" :: "r"(d), "l"(s));
}
#define CP_COMMIT() asm volatile("cp.async.commit_group;" ::: "memory")
#define CP_WAIT1()  asm volatile("cp.async.wait_group 1;" ::: "memory")
#define CP_WAIT0()  asm volatile("cp.async.wait_group 0;" ::: "memory")

__device__ __forceinline__ __half2 tanh2(__half2 x) {
    __half2 r;
    asm("tanh.approx.f16x2 %0, %1;"
        : "=r"(*reinterpret_cast<uint32_t*>(&r))
        : "r"(*reinterpret_cast<const uint32_t*>(&x)));
    return r;
}

// ---------------------------------------------------------------------------
// convert: split inputs + weights into bf16 hi/lo (one float4 per thread)
// ---------------------------------------------------------------------------
__global__ void __launch_bounds__(256) convert_kernel(
    const float* __restrict__ query, const float* __restrict__ enc,
    const float* __restrict__ W_s, const float* __restrict__ W_h,
    const float* __restrict__ W_out)
{
    const int i4 = blockIdx.x * 256 + threadIdx.x;
    const float* src;
    __nv_bfloat16 *dhi, *dlo;
    int off;
    if (i4 < 131072)      { src = query; dhi = g_qhi;  dlo = g_qlo;  off = i4; }
    else if (i4 < 393216) { src = enc;   dhi = g_ehi;  dlo = g_elo;  off = i4 - 131072; }
    else if (i4 < 458752) { src = W_s;   dhi = g_wshi; dlo = g_wslo; off = i4 - 393216; }
    else if (i4 < 524288) { src = W_h;   dhi = g_whhi; dlo = g_whlo; off = i4 - 458752; }
    else                  { src = W_out; dhi = g_wohi; dlo = g_wolo; off = i4 - 524288; }

    const float4 v = reinterpret_cast<const float4*>(src)[off];
    union { __nv_bfloat16 h[4]; uint2 u; } ph, pl;
    bsplit(v.x, ph.h[0], pl.h[0]); bsplit(v.y, ph.h[1], pl.h[1]);
    bsplit(v.z, ph.h[2], pl.h[2]); bsplit(v.w, ph.h[3], pl.h[3]);
    reinterpret_cast<uint2*>(dhi)[off] = ph.u;
    reinterpret_cast<uint2*>(dlo)[off] = pl.u;
}

// ---------------------------------------------------------------------------
// Split-K wmma GEMM (bf16 3-term compensation), fp32 partial output.
// Tile 64x64, 256 threads, 8 warps (warp tile 16x32), K-chunk 32, 2-stage.
// ---------------------------------------------------------------------------
#define PITCH 40
#define TILE_B (64 * PITCH * 2)          // 5120 B
#define AHI_O 0
#define ALO_O (TILE_B)
#define BHI_O (2 * TILE_B)
#define BLO_O (3 * TILE_B)
#define BUF_B (4 * TILE_B)               // 20480 B per stage
#define SMEM_BYTES (2 * BUF_B)           // 40960 B

__device__ __forceinline__ void issue_chunk(
    uint32_t sb,
    const __nv_bfloat16* __restrict__ Ahi, const __nv_bfloat16* __restrict__ Alo,
    const __nv_bfloat16* __restrict__ Bhi, const __nv_bfloat16* __restrict__ Blo,
    int ldb, int m0, int n0, int aoff, int boff, int tid)
{
    const int row = tid >> 2, seg = tid & 3;       // 64 rows x 4 x 16B
    const uint32_t soff = (uint32_t)(row * (PITCH * 2) + seg * 16);
    const size_t ao = (size_t)(m0 + row) * H_ + aoff + seg * 8;
    const size_t bo = (size_t)(n0 + row) * ldb + boff + seg * 8;
    cpa16(sb + AHI_O + soff, Ahi + ao);
    cpa16(sb + ALO_O + soff, Alo + ao);
    cpa16(sb + BHI_O + soff, Bhi + bo);
    cpa16(sb + BLO_O + soff, Blo + bo);
}

__device__ __forceinline__ void gemm_sk(
    char* smem,
    const __nv_bfloat16* __restrict__ Ahi, const __nv_bfloat16* __restrict__ Alo,
    const __nv_bfloat16* __restrict__ Bhi, const __nv_bfloat16* __restrict__ Blo,
    int ldb, float* __restrict__ Cpart,
    int m0, int n0, int akbeg, int bkbeg, int nchunks)
{
    const int tid  = threadIdx.x;
    const int wid  = tid >> 5;
    const int m0w  = (wid >> 1) * 16;    // 4 m-warps x 16 rows
    const int n0w  = (wid & 1) * 32;     // 2 n-warps x 32 cols
    const uint32_t sb = smem_u32(smem);

    wmma::fragment<wmma::accumulator, 16, 16, 16, float> acc[2];
    wmma::fill_fragment(acc[0], 0.0f);
    wmma::fill_fragment(acc[1], 0.0f);

    issue_chunk(sb, Ahi, Alo, Bhi, Blo, ldb, m0, n0, akbeg, bkbeg, tid);
    CP_COMMIT();

    #pragma unroll 1
    for (int it = 0; it < nchunks; ++it) {
        if (it + 1 < nchunks) {
            issue_chunk(sb + ((it + 1) & 1) * BUF_B, Ahi, Alo, Bhi, Blo,
                        ldb, m0, n0, akbeg + (it + 1) * 32, bkbeg + (it + 1) * 32, tid);
            CP_COMMIT();
            CP_WAIT1();
        } else {
            CP_WAIT0();
        }
        __syncthreads();

        const char* buf = smem + (it & 1) * BUF_B;
        const __nv_bfloat16* sAhi = reinterpret_cast<const __nv_bfloat16*>(buf + AHI_O);
        const __nv_bfloat16* sAlo = reinterpret_cast<const __nv_bfloat16*>(buf + ALO_O);
        const __nv_bfloat16* sBhi = reinterpret_cast<const __nv_bfloat16*>(buf + BHI_O);
        const __nv_bfloat16* sBlo = reinterpret_cast<const __nv_bfloat16*>(buf + BLO_O);

        #pragma unroll
        for (int kf = 0; kf < 2; kf++) {
            const int ko = kf * 16;
            wmma::fragment<wmma::matrix_a, 16, 16, 16, __nv_bfloat16, wmma::row_major> ahi, alo;
            wmma::fragment<wmma::matrix_b, 16, 16, 16, __nv_bfloat16, wmma::col_major> bhi[2], blo[2];
            wmma::load_matrix_sync(ahi, &sAhi[m0w * PITCH + ko], PITCH);
            wmma::load_matrix_sync(alo, &sAlo[m0w * PITCH + ko], PITCH);
            #pragma unroll
            for (int ni = 0; ni < 2; ni++) {
                wmma::load_matrix_sync(bhi[ni], &sBhi[(n0w + 16 * ni) * PITCH + ko], PITCH);
                wmma::load_matrix_sync(blo[ni], &sBlo[(n0w + 16 * ni) * PITCH + ko], PITCH);
            }
            #pragma unroll
            for (int ni = 0; ni < 2; ni++) {
                wmma::mma_sync(acc[ni], ahi, bhi[ni], acc[ni]);
                wmma::mma_sync(acc[ni], ahi, blo[ni], acc[ni]);
                wmma::mma_sync(acc[ni], alo, bhi[ni], acc[ni]);
            }
        }
        __syncthreads();
    }

    #pragma unroll
    for (int ni = 0; ni < 2; ni++)
        wmma::store_matrix_sync(
            &Cpart[(size_t)(m0 + m0w) * H_ + n0 + n0w + 16 * ni],
            acc[ni], H_, wmma::mem_row_major);
}

// proj: grid (8, 48, 2). y<16 -> qs partial; else hs partial. kz splits K=512 in 2.
__global__ void __launch_bounds__(256) proj_wmma()
{
    __shared__ __align__(16) char smem[SMEM_BYTES];
    const int n0 = blockIdx.x * 64;
    const int my = blockIdx.y;
    const int kz = blockIdx.z;
    const int kb = kz * 256;
    if (my < 16)
        gemm_sk(smem, g_qhi, g_qlo, g_wshi, g_wslo, H_,
                g_ppq[kz], my * 64, n0, kb, kb, 8);
    else
        gemm_sk(smem, g_ehi, g_elo, g_whhi, g_whlo, H_,
                g_pph[kz], (my - 16) * 64, n0, kb, kb, 8);
}

// preduce: hs = fp16(pph0+pph1)  (262144 float4s -> 1024 blocks)
__global__ void __launch_bounds__(256) preduce_kernel()
{
    const int j = blockIdx.x * 256 + threadIdx.x;
    const float4 a = reinterpret_cast<const float4*>(g_pph[0])[j];
    const float4 b = reinterpret_cast<const float4*>(g_pph[1])[j];
    const __half2 h0 = __floats2half2_rn(a.x + b.x, a.y + b.y);
    const __half2 h1 = __floats2half2_rn(a.z + b.z, a.w + b.w);
    uint2 st;
    st.x = *reinterpret_cast<const uint32_t*>(&h0);
    st.y = *reinterpret_cast<const uint32_t*>(&h1);
    reinterpret_cast<uint2*>(g_hsh)[j] = st;
}

// out: grid (8, 16, 4). kz<2 reads ctx, kz>=2 reads query (concat-aligned split-K).
__global__ void __launch_bounds__(256) out_wmma()
{
    __shared__ __align__(16) char smem[SMEM_BYTES];
    const int kz = blockIdx.z;
    const __nv_bfloat16* Ahi = (kz < 2) ? g_chi : g_qhi;
    const __nv_bfloat16* Alo = (kz < 2) ? g_clo : g_qlo;
    gemm_sk(smem, Ahi, Alo, g_wohi, g_wolo, 2 * H_,
            g_po[kz], blockIdx.y * 64, blockIdx.x * 64,
            (kz & 1) * 256, kz * 256, 8);
}

// oreduce: out = tanh(p0+p1+p2+p3 + bias)  (131072 float4s -> 512 blocks)
__global__ void __launch_bounds__(256) oreduce_kernel(
    const float* __restrict__ bias, float* __restrict__ out)
{
    const int i4 = blockIdx.x * 256 + threadIdx.x;
    const float4 p0 = reinterpret_cast<const float4*>(g_po[0])[i4];
    const float4 p1 = reinterpret_cast<const float4*>(g_po[1])[i4];
    const float4 p2 = reinterpret_cast<const float4*>(g_po[2])[i4];
    const float4 p3 = reinterpret_cast<const float4*>(g_po[3])[i4];
    const float4 bb = *reinterpret_cast<const float4*>(&bias[(i4 & 127) * 4]);
    float4 o;
    o.x = tanhf(p0.x + p1.x + p2.x + p3.x + bb.x);
    o.y = tanhf(p0.y + p1.y + p2.y + p3.y + bb.y);
    o.z = tanhf(p0.z + p1.z + p2.z + p3.z + bb.z);
    o.w = tanhf(p0.w + p1.w + p2.w + p3.w + bb.w);
    reinterpret_cast<float4*>(out)[i4] = o;
}

// ---------------------------------------------------------------------------
// Fused attention, TT=4, 512 threads, 256 blocks, 2 CTAs/SM.
// Pass1 fully packed fp16: hs stored as half in smem, HADD2 + tanh.f16x2 +
// HFMA2 (two alternating half2 accumulators, 4-deep), fp32 cross-lane reduce.
// Scores transposed [S][TT]; pass2 fp32 unchanged. qreg fuses qs split-K add.
// smem: 16KB (half hs double buffer) + 4KB scores.
// ---------------------------------------------------------------------------
#define TT 4
#define SC 8

__global__ void __launch_bounds__(512, 2) attn_kernel(
    const float* __restrict__ enc, const float* __restrict__ v,
    const int* __restrict__ lens)
{
    __shared__ __align__(16) __half sh_hs[2][SC * H_];   // 2 x 8 KB
    __shared__ float sh_sc[S_][TT];                      // 4 KB (transposed)
    __shared__ float sh_rsum[TT];

    const int b     = blockIdx.y;
    const int t0    = blockIdx.x * TT;
    const int tid   = threadIdx.x;
    const int lane  = tid & 31;
    const int wid   = tid >> 5;               // 0..15
    const int t_loc = wid >> 2;               // 0..3
    const int squad = wid & 3;                // 0..3

    const int len = lens[b];
    const int nch = (len + SC - 1) / SC;      // 16..32 chunks

    // q (fused split-K partial sum) + v packed to half2.
    // half2 index owned: c*128 + lane*4 + k  (c in 0..1, k in 0..3)
    __half2 qh[8], vh[8];
    {
        const size_t ro = (size_t)(b * T_ + t0 + t_loc) * H_;
        #pragma unroll
        for (int c = 0; c < 2; c++) {
            #pragma unroll
            for (int k2 = 0; k2 < 2; k2++) {
                const int off = c * 256 + lane * 8 + k2 * 4;
                const float4 p0 = *reinterpret_cast<const float4*>(&g_ppq[0][ro + off]);
                const float4 p1 = *reinterpret_cast<const float4*>(&g_ppq[1][ro + off]);
                const float4 vv = *reinterpret_cast<const float4*>(&v[off]);
                qh[c * 4 + k2 * 2 + 0] = __floats2half2_rn(p0.x + p1.x, p0.y + p1.y);
                qh[c * 4 + k2 * 2 + 1] = __floats2half2_rn(p0.z + p1.z, p0.w + p1.w);
                vh[c * 4 + k2 * 2 + 0] = __floats2half2_rn(vv.x, vv.y);
                vh[c * 4 + k2 * 2 + 1] = __floats2half2_rn(vv.z, vv.w);
            }
        }
    }

    const __half* hsb = g_hsh + (size_t)b * S_ * H_;
    const float* encb = enc + (size_t)b * S_ * H_;

    // ---- Pass 1: double-buffered (1 uint4 per thread per chunk) ----
    uint4 r = reinterpret_cast<const uint4*>(hsb)[tid];
    reinterpret_cast<uint4*>(&sh_hs[0][0])[tid] = r;

    #pragma unroll 1
    for (int it = 0; it < nch; ++it) {
        if (it + 1 < nch)
            r = reinterpret_cast<const uint4*>(hsb + (size_t)(it + 1) * SC * H_)[tid];
        __syncthreads();   // buf[it&1] ready; all warps done with buf[(it+1)&1]

        const __half* base = sh_hs[it & 1];
        const int s0 = it * SC;
        #pragma unroll
        for (int i = 0; i < SC / 4; i++) {     // warp owns 2 of the 8 rows
            const int ro = squad * (SC / 4) + i;
            const uint4* hrow = reinterpret_cast<const uint4*>(&base[ro * H_]);
            __half2 accA = __float2half2_rn(0.0f);
            __half2 accB = __float2half2_rn(0.0f);
            #pragma unroll
            for (int c = 0; c < 2; c++) {
                const uint4 hv = hrow[c * 32 + lane];
                const __half2 h0 = *reinterpret_cast<const __half2*>(&hv.x);
                const __half2 h1 = *reinterpret_cast<const __half2*>(&hv.y);
                const __half2 h2 = *reinterpret_cast<const __half2*>(&hv.z);
                const __half2 h3 = *reinterpret_cast<const __half2*>(&hv.w);
                accA = __hfma2(tanh2(__hadd2(qh[c * 4 + 0], h0)), vh[c * 4 + 0], accA);
                accB = __hfma2(tanh2(__hadd2(qh[c * 4 + 1], h1)), vh[c * 4 + 1], accB);
                accA = __hfma2(tanh2(__hadd2(qh[c * 4 + 2], h2)), vh[c * 4 + 2], accA);
                accB = __hfma2(tanh2(__hadd2(qh[c * 4 + 3], h3)), vh[c * 4 + 3], accB);
            }
            const float2 fA = __half22float2(accA);
            const float2 fB = __half22float2(accB);
            float acc = (fA.x + fA.y) + (fB.x + fB.y);
            acc += __shfl_xor_sync(0xffffffffu, acc, 16);
            acc += __shfl_xor_sync(0xffffffffu, acc, 8);
            acc += __shfl_xor_sync(0xffffffffu, acc, 4);
            acc += __shfl_xor_sync(0xffffffffu, acc, 2);
            acc += __shfl_xor_sync(0xffffffffu, acc, 1);
            if (lane == 0) sh_sc[s0 + ro][t_loc] = acc;
        }

        if (it + 1 < nch)
            reinterpret_cast<uint4*>(&sh_hs[(it + 1) & 1][0])[tid] = r;
    }
    __syncthreads();

    // ---- Softmax (warps 0-3, one per t row) ----
    if (wid < TT) {
        const int t = wid;
        float vals[S_ / 32];
        float m = -1e30f;
        #pragma unroll
        for (int i = 0; i < S_ / 32; i++) {
            const int s = lane + 32 * i;
            const float sc = (s < len) ? sh_sc[s][t] : -1e30f;
            vals[i] = sc;
            m = fmaxf(m, sc);
        }
        #pragma unroll
        for (int o = 16; o; o >>= 1) m = fmaxf(m, __shfl_xor_sync(0xffffffffu, m, o));
        float sum = 0.f;
        #pragma unroll
        for (int i = 0; i < S_ / 32; i++) {
            const int s = lane + 32 * i;
            const float e = (s < len) ? __expf(vals[i] - m) : 0.f;
            sh_sc[s][t] = e;
            sum += e;
        }
        #pragma unroll
        for (int o = 16; o; o >>= 1) sum += __shfl_xor_sync(0xffffffffu, sum, o);
        if (lane == 0) sh_rsum[t] = 1.0f / sum;
    }
    __syncthreads();

    // ---- Pass 2: context; 4 groups over s-quarters of [0,len) ----
    const int g  = tid >> 7;                  // 0..3
    const int c4 = tid & 127;
    const int sbeg = (g * len) >> 2;
    const int send = ((g + 1) * len) >> 2;

    float4 acc4[TT];
    #pragma unroll
    for (int t = 0; t < TT; t++) acc4[t] = make_float4(0.f, 0.f, 0.f, 0.f);

    #pragma unroll 4
    for (int s = sbeg; s < send; s++) {
        const float4 e4 = *reinterpret_cast<const float4*>(&encb[(size_t)s * H_ + c4 * 4]);
        const float4 w4 = *reinterpret_cast<const float4*>(&sh_sc[s][0]);
        acc4[0].x = fmaf(w4.x, e4.x, acc4[0].x);
        acc4[0].y = fmaf(w4.x, e4.y, acc4[0].y);
        acc4[0].z = fmaf(w4.x, e4.z, acc4[0].z);
        acc4[0].w = fmaf(w4.x, e4.w, acc4[0].w);
        acc4[1].x = fmaf(w4.y, e4.x, acc4[1].x);
        acc4[1].y = fmaf(w4.y, e4.y, acc4[1].y);
        acc4[1].z = fmaf(w4.y, e4.z, acc4[1].z);
        acc4[1].w = fmaf(w4.y, e4.w, acc4[1].w);
        acc4[2].x = fmaf(w4.z, e4.x, acc4[2].x);
        acc4[2].y = fmaf(w4.z, e4.y, acc4[2].y);
        acc4[2].z = fmaf(w4.z, e4.z, acc4[2].z);
        acc4[2].w = fmaf(w4.z, e4.w, acc4[2].w);
        acc4[3].x = fmaf(w4.w, e4.x, acc4[3].x);
        acc4[3].y = fmaf(w4.w, e4.y, acc4[3].y);
        acc4[3].z = fmaf(w4.w, e4.z, acc4[3].z);
        acc4[3].w = fmaf(w4.w, e4.w, acc4[3].w);
    }

    // combine via smem (reuse the two 8KB half buffers as float scratch)
    float* bufA = reinterpret_cast<float*>(&sh_hs[0][0]);   // 8 KB = 2048 floats
    float* bufB = reinterpret_cast<float*>(&sh_hs[1][0]);
    if (g == 1) {
        #pragma unroll
        for (int t = 0; t < TT; t++)
            *reinterpret_cast<float4*>(&bufA[(t * 128 + c4) * 4]) = acc4[t];
    }
    if (g == 3) {
        #pragma unroll
        for (int t = 0; t < TT; t++)
            *reinterpret_cast<float4*>(&bufB[(t * 128 + c4) * 4]) = acc4[t];
    }
    __syncthreads();
    if (g == 0) {
        #pragma unroll
        for (int t = 0; t < TT; t++) {
            const float4 p = *reinterpret_cast<const float4*>(&bufA[(t * 128 + c4) * 4]);
            acc4[t].x += p.x; acc4[t].y += p.y; acc4[t].z += p.z; acc4[t].w += p.w;
        }
    }
    if (g == 2) {
        #pragma unroll
        for (int t = 0; t < TT; t++) {
            const float4 p = *reinterpret_cast<const float4*>(&bufB[(t * 128 + c4) * 4]);
            acc4[t].x += p.x; acc4[t].y += p.y; acc4[t].z += p.z; acc4[t].w += p.w;
            *reinterpret_cast<float4*>(&bufB[(t * 128 + c4) * 4]) = acc4[t];
        }
    }
    __syncthreads();
    if (g == 0) {
        #pragma unroll
        for (int t = 0; t < TT; t++) {
            const float4 p = *reinterpret_cast<const float4*>(&bufB[(t * 128 + c4) * 4]);
            const float rs = sh_rsum[t];
            float4 o;
            o.x = (acc4[t].x + p.x) * rs;
            o.y = (acc4[t].y + p.y) * rs;
            o.z = (acc4[t].z + p.z) * rs;
            o.w = (acc4[t].w + p.w) * rs;
            union { __nv_bfloat16 h[4]; uint2 u; } ph, pl;
            bsplit(o.x, ph.h[0], pl.h[0]); bsplit(o.y, ph.h[1], pl.h[1]);
            bsplit(o.z, ph.h[2], pl.h[2]); bsplit(o.w, ph.h[3], pl.h[3]);
            const size_t off = (size_t)(b * T_ + t0 + t) * H_ + c4 * 4;
            *reinterpret_cast<uint2*>(&g_chi[off]) = ph.u;
            *reinterpret_cast<uint2*>(&g_clo[off]) = pl.u;
        }
    }
}

// ---------------------------------------------------------------------------
extern "C" void kernel_launch(void* const* d_in, const int* in_sizes, int n_in,
                              void* d_out, int out_size)
{
    const float* query = (const float*)d_in[0];
    const float* enc   = (const float*)d_in[1];
    const int*   lens  = (const int*)d_in[2];
    const float* W_s   = (const float*)d_in[3];
    const float* W_h   = (const float*)d_in[4];
    const float* v     = (const float*)d_in[5];
    const float* W_out = (const float*)d_in[6];
    const float* b_out = (const float*)d_in[7];
    float* out = (float*)d_out;

    convert_kernel<<<2560, 256>>>(query, enc, W_s, W_h, W_out);
    proj_wmma<<<dim3(8, 48, 2), 256>>>();
    preduce_kernel<<<1024, 256>>>();
    attn_kernel<<<dim3(T_ / TT, B_), 512>>>(enc, v, lens);
    out_wmma<<<dim3(8, 16, 4), 256>>>();
    oreduce_kernel<<<512, 256>>>(b_out, out);
}